// round 14
// baseline (speedup 1.0000x reference)
#include <cuda_runtime.h>
#include <cstdint>

#define NNODES 20000
#define NEDGES 320000
#define DM 128
#define PREDL 24

// ---------------- device scratch ----------------------------------------------
__device__ float g_h[NNODES * DM];
__device__ float g_e[(size_t)NEDGES * DM];
__device__ float g_agg[NNODES * DM];    // PERMUTED layout (matches store_perm)
__device__ float g_cnt[NNODES];
__device__ float g_hs[NNODES * DM];     // (h @ Ws0) permuted
__device__ float g_hr[NNODES * DM];     // (h @ Wr0) permuted
#define CWL 82176
__device__ float g_cw[2 * CWL];         // composed weights (fp32)
__device__ float g_wt[69 * 4096];       // fragment-layout weights (tf32)

// g_wt chunk offsets
#define W_E0(l)  ((l) * 4)
#define W_M1E(l) (8 + (l) * 4)
#define W_N0(l)  (16 + (l) * 8)
#define W_M1N(l) (32 + (l) * 4)
#define W_S0(l)  (40 + (l) * 8)
#define W_R0(l)  (44 + (l) * 8)
#define W_OUT    56
#define W_EMB    60

// ---------------- smem float offsets (M=64 tile) --------------------------------
#define F_SUM 128               // 256
#define F_SQ  384               // 256
#define F_PAR 640               // 1152 params
#define F_W   1792              // 2 x 4096 W double buffer
#define F_T   (F_W + 8192)      // 4 x 2048 activation tile
#define SMEMB ((F_T + 8192) * 4)   // 72704 B -> 3 CTAs/SM

// ---------------- helpers ------------------------------------------------------
__device__ __forceinline__ uint32_t tfr(float x) {
    uint32_t r;
    asm("cvt.rna.tf32.f32 %0, %1;" : "=r"(r) : "f"(x));
    return r;
}
__device__ __forceinline__ float tff(float x) { return __uint_as_float(tfr(x)); }

__device__ __forceinline__ uint32_t smem_u32(const void* p) {
    uint32_t a;
    asm("{ .reg .u64 t; cvta.to.shared.u64 t, %1; cvt.u32.u64 %0, t; }"
        : "=r"(a) : "l"(p));
    return a;
}

__device__ __forceinline__ void mma8(float c[4], uint32_t a0, uint32_t a1,
                                     uint32_t a2, uint32_t a3,
                                     uint32_t b0, uint32_t b1) {
    asm volatile(
        "mma.sync.aligned.m16n8k8.row.col.f32.tf32.tf32.f32 "
        "{%0,%1,%2,%3}, {%4,%5,%6,%7}, {%8,%9}, {%0,%1,%2,%3};"
        : "+f"(c[0]), "+f"(c[1]), "+f"(c[2]), "+f"(c[3])
        : "r"(a0), "r"(a1), "r"(a2), "r"(a3), "r"(b0), "r"(b1));
}

// HW tanh (MUFU, sm_75+)
__device__ __forceinline__ float tanh_hw(float x) {
    float r;
    asm("tanh.approx.f32 %0, %1;" : "=f"(r) : "f"(x));
    return r;
}
__device__ __forceinline__ float geluf(float x) {
    float x3 = x * x * x;
    return 0.5f * x * (1.0f + tanh_hw(fmaf(0.044715f * 0.7978845608028654f, x3,
                                           0.7978845608028654f * x)));
}

__device__ __forceinline__ int fAg(int g) { return (g ^ (g >> 2)) & 3; }

// A-fragment index in a 2048-float chunk (64 rows x 32 k)
__device__ __forceinline__ int aidx(int row, int kl) {
    int wm = row >> 5, mm = (row >> 4) & 1, r8 = (row >> 3) & 1, g = row & 7;
    int kk = kl >> 3, k4 = (kl >> 2) & 1, tig = kl & 3;
    return (((kk * 2 + wm) * 2 + mm) << 7) + ((g * 4 + (tig ^ fAg(g))) << 2)
           + r8 + (k4 << 1);
}
// B-fragment index in a 4096-float chunk
__device__ __forceinline__ int bidx(int kl, int n) {
    int kk = kl >> 3, k4 = (kl >> 2) & 1, tig = kl & 3;
    int wn = n >> 5, ntp = (n >> 4) & 1, ntb = (n >> 3) & 1, gq = n & 7;
    return (((kk * 4 + wn) * 2 + ntp) << 7) + ((gq * 4 + tig) << 2)
           + ntb * 2 + k4;
}

#define CP16(daddr, src) asm volatile( \
    "cp.async.cg.shared.global [%0], [%1], 16;" :: "r"(daddr), "l"(src))
#define CP_COMMIT() asm volatile("cp.async.commit_group;" ::: "memory")
#define CP_WAIT0()  asm volatile("cp.async.wait_group 0;" ::: "memory")

// one 4096-float W chunk via cp.async (256 threads x 4 x 16B)
__device__ __forceinline__ void copy_w_async(uint32_t dsts,
                                             const float* __restrict__ src,
                                             int tid) {
    CP16(dsts + tid * 16, src + tid * 4);
    CP16(dsts + (tid + 256) * 16, src + (tid + 256) * 4);
    CP16(dsts + (tid + 512) * 16, src + (tid + 512) * 4);
    CP16(dsts + (tid + 768) * 16, src + (tid + 768) * 4);
}

// one 32-wide K chunk; warp covers 32 rows x 32 cols (A chunk = 2048 floats)
__device__ __forceinline__ void chunk_mma(const float* __restrict__ sA,
                                          const float* __restrict__ sW,
                                          float C[2][4][4], int wm, int wn,
                                          int lane, int pl4) {
#pragma unroll
    for (int kk = 0; kk < 4; kk++) {
        float4 b0 = *(const float4*)(sW + (((kk * 4 + wn) * 2 + 0) << 7)
                                     + (lane << 2));
        float4 b1 = *(const float4*)(sW + (((kk * 4 + wn) * 2 + 1) << 7)
                                     + (lane << 2));
#pragma unroll
        for (int mm = 0; mm < 2; mm++) {
            float4 av = *(const float4*)(sA + (((kk * 2 + wm) * 2 + mm) << 7) + pl4);
            uint32_t a0 = __float_as_uint(av.x), a1 = __float_as_uint(av.y);
            uint32_t a2 = __float_as_uint(av.z), a3 = __float_as_uint(av.w);
            mma8(C[mm][0], a0, a1, a2, a3,
                 __float_as_uint(b0.x), __float_as_uint(b0.y));
            mma8(C[mm][1], a0, a1, a2, a3,
                 __float_as_uint(b0.z), __float_as_uint(b0.w));
            mma8(C[mm][2], a0, a1, a2, a3,
                 __float_as_uint(b1.x), __float_as_uint(b1.y));
            mma8(C[mm][3], a0, a1, a2, a3,
                 __float_as_uint(b1.z), __float_as_uint(b1.w));
        }
    }
}

__device__ __forceinline__ void stage_Af8(float* chunk, const float* __restrict__ src,
                                          int r, int q4) {
    float4 v0 = *(const float4*)(src);
    float4 v1 = *(const float4*)(src + 4);
    chunk[aidx(r, q4 * 8 + 0)] = tff(v0.x);
    chunk[aidx(r, q4 * 8 + 1)] = tff(v0.y);
    chunk[aidx(r, q4 * 8 + 2)] = tff(v0.z);
    chunk[aidx(r, q4 * 8 + 3)] = tff(v0.w);
    chunk[aidx(r, q4 * 8 + 4)] = tff(v1.x);
    chunk[aidx(r, q4 * 8 + 5)] = tff(v1.y);
    chunk[aidx(r, q4 * 8 + 6)] = tff(v1.z);
    chunk[aidx(r, q4 * 8 + 7)] = tff(v1.w);
}

// stage 8 floats of PERMUTED agg block (phys j -> logical kl) with scale
__device__ __forceinline__ void stage_Agg_perm(float* chunk,
                                               const float* __restrict__ src,
                                               int r, int q4, float sc) {
    float4 v0 = *(const float4*)(src);
    float4 v1 = *(const float4*)(src + 4);
    float v[8] = {v0.x, v0.y, v0.z, v0.w, v1.x, v1.y, v1.z, v1.w};
#pragma unroll
    for (int j = 0; j < 8; j++) {
        int kl = (j >> 1) * 8 + q4 * 2 + (j & 1);
        chunk[aidx(r, kl)] = tff(v[j] * sc);
    }
}

// stage 32 cols of a row EXACT into A-frag chunk
__device__ __forceinline__ void stage_E32(float* chunk, const float* __restrict__ src,
                                          int r) {
#pragma unroll
    for (int i = 0; i < 8; i++) {
        float4 v = *(const float4*)(src + i * 4);
        chunk[aidx(r, i * 4 + 0)] = v.x;
        chunk[aidx(r, i * 4 + 1)] = v.y;
        chunk[aidx(r, i * 4 + 2)] = v.z;
        chunk[aidx(r, i * 4 + 3)] = v.w;
    }
}

__device__ __forceinline__ void write_T(float C[2][4][4], float* smf, int fbase,
                                        int wm, int wn, int lane, int cvt) {
    int g = lane >> 2, q = lane & 3;
#pragma unroll
    for (int mm = 0; mm < 2; mm++)
#pragma unroll
        for (int hx = 0; hx < 2; hx++) {
            int row = wm * 32 + mm * 16 + hx * 8 + g;
#pragma unroll
            for (int nt = 0; nt < 4; nt++)
#pragma unroll
                for (int s = 0; s < 2; s++) {
                    int col = wn * 32 + nt * 8 + q * 2 + s;
                    float v = C[mm][nt][hx * 2 + s];
                    smf[fbase + (col >> 5) * 2048 + aidx(row, col & 31)] =
                        cvt ? tff(v) : v;
                }
        }
}

__device__ __forceinline__ void gelu_ln_ep(float C[2][4][4], float* smf,
                                           int wm, int wn, int lane,
                                           int pb, int pg, int pbe) {
    int g = lane >> 2, q = lane & 3;
    float* sSum = smf + F_SUM;
    float* sSq  = smf + F_SQ;
#pragma unroll
    for (int mm = 0; mm < 2; mm++)
#pragma unroll
        for (int hx = 0; hx < 2; hx++) {
            float ps = 0.f, pq = 0.f;
#pragma unroll
            for (int nt = 0; nt < 4; nt++)
#pragma unroll
                for (int s = 0; s < 2; s++) {
                    int col = wn * 32 + nt * 8 + q * 2 + s;
                    float v = geluf(C[mm][nt][hx * 2 + s] + smf[pb + col]);
                    C[mm][nt][hx * 2 + s] = v;
                    ps += v; pq += v * v;
                }
            ps += __shfl_xor_sync(0xffffffffu, ps, 1);
            ps += __shfl_xor_sync(0xffffffffu, ps, 2);
            pq += __shfl_xor_sync(0xffffffffu, pq, 1);
            pq += __shfl_xor_sync(0xffffffffu, pq, 2);
            if (q == 0) {
                int row = wm * 32 + mm * 16 + hx * 8 + g;
                sSum[row * 4 + wn] = ps;
                sSq[row * 4 + wn]  = pq;
            }
        }
    __syncthreads();
#pragma unroll
    for (int mm = 0; mm < 2; mm++)
#pragma unroll
        for (int hx = 0; hx < 2; hx++) {
            int row = wm * 32 + mm * 16 + hx * 8 + g;
            float m = (sSum[row * 4] + sSum[row * 4 + 1]
                       + sSum[row * 4 + 2] + sSum[row * 4 + 3]) * (1.0f / 128.0f);
            float qv = (sSq[row * 4] + sSq[row * 4 + 1]
                        + sSq[row * 4 + 2] + sSq[row * 4 + 3]) * (1.0f / 128.0f);
            float rs = rsqrtf(qv - m * m + 1e-5f);
#pragma unroll
            for (int nt = 0; nt < 4; nt++)
#pragma unroll
                for (int s = 0; s < 2; s++) {
                    int col = wn * 32 + nt * 8 + q * 2 + s;
                    C[mm][nt][hx * 2 + s] =
                        (C[mm][nt][hx * 2 + s] - m) * rs * smf[pg + col] + smf[pbe + col];
                }
        }
}

#define ZERO_C(C) do { \
    _Pragma("unroll") for (int _m = 0; _m < 2; _m++) \
    _Pragma("unroll") for (int _n = 0; _n < 4; _n++) \
    _Pragma("unroll") for (int _s = 0; _s < 4; _s++) (C)[_m][_n][_s] = 0.f; } while (0)

// streamed K=128 GEMM: A resident in T chunks, W double-buffered
__device__ __forceinline__ void gemm_T4s(float* smf, uint32_t sb,
                                         const float* __restrict__ W,
                                         float C[2][4][4], int tid,
                                         int wm, int wn, int lane, int pl4) {
    copy_w_async(sb + F_W * 4, W, tid); CP_COMMIT();
    CP_WAIT0(); __syncthreads();
#pragma unroll 1
    for (int c = 0; c < 4; c++) {
        if (c < 3) {
            copy_w_async(sb + F_W * 4 + ((c + 1) & 1) * 16384, W + (c + 1) * 4096, tid);
            CP_COMMIT();
        }
        chunk_mma(smf + F_T + c * 2048, smf + F_W + (c & 1) * 4096,
                  C, wm, wn, lane, pl4);
        CP_WAIT0();
        __syncthreads();
    }
}

#define ROWBASE(r, rb, fg) \
    int rb = (((r) >> 5) * 2 + (((r) >> 4) & 1)) * 128 + ((r) & 7) * 16 \
             + (((r) >> 3) & 1); \
    int fg = fAg((r) & 7)
#define AFIDX(rb, fg, j) \
    (((j) >> 3) * 512 + (rb) + ((((j) & 3) ^ (fg)) << 2) + ((((j) >> 2) & 1) << 1))

#define RED4(p, f4) asm volatile( \
    "red.global.add.v4.f32 [%0], {%1,%2,%3,%4};" \
    :: "l"(p), "f"((f4).x), "f"((f4).y), "f"((f4).z), "f"((f4).w) : "memory")

// direct permuted store of C fragments to gout
__device__ __forceinline__ void store_perm(const float C[2][4][4],
                                           float* __restrict__ gout, int base,
                                           int wm, int wn, int g, int q) {
#pragma unroll
    for (int mm = 0; mm < 2; mm++)
#pragma unroll
        for (int hx = 0; hx < 2; hx++) {
            int row = wm * 32 + mm * 16 + hx * 8 + g;
            if (base + row >= NNODES) continue;
            float* go = gout + (size_t)(base + row) * DM + wn * 32 + q * 8;
            float4 f0, f1;
            f0.x = C[mm][0][hx * 2 + 0]; f0.y = C[mm][0][hx * 2 + 1];
            f0.z = C[mm][1][hx * 2 + 0]; f0.w = C[mm][1][hx * 2 + 1];
            f1.x = C[mm][2][hx * 2 + 0]; f1.y = C[mm][2][hx * 2 + 1];
            f1.z = C[mm][3][hx * 2 + 0]; f1.w = C[mm][3][hx * 2 + 1];
            *(float4*)go = f0;
            *(float4*)(go + 4) = f1;
        }
}

// ---------------- compose: fp32 weight products --------------------------------
__global__ void compose_k(const float* __restrict__ epw, const float* __restrict__ epb,
                          const float* __restrict__ emw, const float* __restrict__ emb_b,
                          const float* __restrict__ npw, const float* __restrict__ npb,
                          const float* __restrict__ nmw, const float* __restrict__ nmb,
                          float* __restrict__ cw) {
    int bi = blockIdx.x, j = threadIdx.x;
    int l = bi / 642, rr = bi % 642;
    const float *A, *B;
    float* out;
    float extra = 0.f;
    if (rr < 384) {
        A = epw + (size_t)l * 384 * 128 + rr * 128;
        B = emw + (l * 2) * 16384;
        out = cw + l * CWL + rr * 128;
    } else if (rr < 640) {
        int r2 = rr - 384;
        A = npw + (size_t)l * 256 * 128 + r2 * 128;
        B = nmw + (l * 2) * 16384;
        out = cw + l * CWL + 49152 + r2 * 128;
    } else if (rr == 640) {
        A = epb + l * 128; B = emw + (l * 2) * 16384;
        out = cw + l * CWL + 81920;
        extra = emb_b[(l * 2) * 128 + j];
    } else {
        A = npb + l * 128; B = nmw + (l * 2) * 16384;
        out = cw + l * CWL + 82048;
        extra = nmb[(l * 2) * 128 + j];
    }
    float acc = extra;
    for (int k = 0; k < 128; k++) acc += A[k] * B[k * 128 + j];
    out[j] = acc;
}

// ---------------- prep: all weights -> B-frag chunks; zero cnt -----------------
__global__ void prep_frag(const float* __restrict__ cw,
                          const float* __restrict__ emw,
                          const float* __restrict__ nmw,
                          const float* __restrict__ mow,
                          const float* __restrict__ wemb,
                          float* __restrict__ wt, float* __restrict__ cnt) {
    int b = blockIdx.x, tid = threadIdx.x;
    if (b < 69) {
        const float* M; int c;
        if (b < 8)       { int l = b >> 2; c = b & 3; M = cw + l * CWL; }
        else if (b < 16) { int l = (b - 8) >> 2; c = (b - 8) & 3;
                           M = emw + (l * 2 + 1) * 16384; }
        else if (b < 32) { int l = (b - 16) >> 3; c = (b - 16) & 7;
                           M = cw + l * CWL + 49152; }
        else if (b < 40) { int l = (b - 32) >> 2; c = (b - 32) & 3;
                           M = nmw + (l * 2 + 1) * 16384; }
        else if (b < 56) { int l = (b - 40) >> 3; int s = (b - 40) & 7;
                           c = s & 3; M = cw + l * CWL + 16384 + (s >> 2) * 16384; }
        else if (b < 60) { c = b - 56; M = mow; }
        else             { c = b - 60; M = wemb; }
        int kl = tid >> 3, n0 = (tid & 7) * 16;
#pragma unroll
        for (int j = 0; j < 16; j++) {
            int n = n0 + j;
            wt[b * 4096 + bidx(kl, n)] = tff(M[(c * 32 + kl) * 128 + n]);
        }
    } else {
        int i = (b - 69) * 256 + tid;
        if (i < NNODES) cnt[i] = 0.f;
    }
}

// merged: zero agg (first 2500 blocks) + in-degree count (rest)
__global__ void init_k(float4* __restrict__ agg4, const int* __restrict__ rcv,
                       float* __restrict__ cnt, int do_count) {
    int b = blockIdx.x;
    if (b < 2500) {
        int i = b * 256 + threadIdx.x;
        if (i < NNODES * 32) agg4[i] = make_float4(0.f, 0.f, 0.f, 0.f);
    } else if (do_count) {
        int i = (b - 2500) * 256 + threadIdx.x;
        if (i < NEDGES) atomicAdd(cnt + rcv[i], 1.0f);
    }
}

// ---------------- edge kernel (64 edges per CTA) --------------------------------
__global__ __launch_bounds__(256, 3) void edge_k(
    float* __restrict__ e, const float* __restrict__ edges,
    const int* __restrict__ snd, const int* __restrict__ rcv,
    const float* __restrict__ hs0, const float* __restrict__ hr0,
    const float* __restrict__ wem, const float* __restrict__ bem,
    const float* __restrict__ wE0, const float* __restrict__ b0c,
    const float* __restrict__ g0, const float* __restrict__ be0,
    const float* __restrict__ wM1, const float* __restrict__ b1,
    const float* __restrict__ g1, const float* __restrict__ be1,
    float* __restrict__ agg, int layer0)
{
    extern __shared__ float smf[];
    uint32_t sb = smem_u32(smf);
    int tid = threadIdx.x, lane = tid & 31, wid = tid >> 5;
    int wm = wid >> 2, wn = wid & 3;
    int g = lane >> 2, q = lane & 3;
    int pl4 = (g * 4 + (q ^ fAg(g))) << 2;
    int base = blockIdx.x * 64;
    int r = tid >> 2, q4 = tid & 3;

    // per-thread row indices (L1-hit LDG, no smem round trip)
    int sIdx[2][2], rIdx[2][2];
#pragma unroll
    for (int mm = 0; mm < 2; mm++)
#pragma unroll
        for (int hx = 0; hx < 2; hx++) {
            int row = wm * 32 + mm * 16 + hx * 8 + g;
            sIdx[mm][hx] = __ldg(snd + base + row);
            rIdx[mm][hx] = __ldg(rcv + base + row);
        }
    if (tid < 128) {
        float* p = smf + F_PAR;
        p[tid] = b0c[tid];       p[128 + tid] = g0[tid];
        p[256 + tid] = be0[tid]; p[384 + tid] = b1[tid];
        p[512 + tid] = g1[tid];  p[640 + tid] = be1[tid];
        if (layer0) {
            p[768 + tid]  = wem[tid];
            p[896 + tid]  = wem[128 + tid];
            p[1024 + tid] = bem[tid];
        }
    }
    if (layer0) {
        __syncthreads();   // wem/bem visible
        float2 xy = *(const float2*)(edges + 2 * (size_t)(base + r));
        const float* w0 = smf + F_PAR + 768;
        const float* w1 = smf + F_PAR + 896;
        const float* bb = smf + F_PAR + 1024;
        float* Tc = smf + F_T + q4 * 2048;
#pragma unroll
        for (int i = 0; i < 32; i++) {
            int col = q4 * 32 + i;
            Tc[aidx(r, i)] =
                tff(fmaf(xy.x, w0[col], fmaf(xy.y, w1[col], bb[col])));
        }
    } else {
        stage_E32(smf + F_T + q4 * 2048,
                  e + (size_t)(base + r) * DM + q4 * 32, r);
    }
    __syncthreads();

    // C init = gathered hs0p + hr0p (permuted layout, coalesced 32B)
    float C[2][4][4];
#pragma unroll
    for (int mm = 0; mm < 2; mm++)
#pragma unroll
        for (int hx = 0; hx < 2; hx++) {
            const float4* hp = (const float4*)(hs0 + (size_t)sIdx[mm][hx] * DM
                                               + wn * 32 + q * 8);
            const float4* rp = (const float4*)(hr0 + (size_t)rIdx[mm][hx] * DM
                                               + wn * 32 + q * 8);
            float4 a0 = hp[0], a1 = hp[1], c0 = rp[0], c1 = rp[1];
            C[mm][0][hx * 2 + 0] = a0.x + c0.x;
            C[mm][0][hx * 2 + 1] = a0.y + c0.y;
            C[mm][1][hx * 2 + 0] = a0.z + c0.z;
            C[mm][1][hx * 2 + 1] = a0.w + c0.w;
            C[mm][2][hx * 2 + 0] = a1.x + c1.x;
            C[mm][2][hx * 2 + 1] = a1.y + c1.y;
            C[mm][3][hx * 2 + 0] = a1.z + c1.z;
            C[mm][3][hx * 2 + 1] = a1.w + c1.w;
        }

    gemm_T4s(smf, sb, wE0, C, tid, wm, wn, lane, pl4);   // += e @ We0
    gelu_ln_ep(C, smf, wm, wn, lane, F_PAR, F_PAR + 128, F_PAR + 256);
    write_T(C, smf, F_T, wm, wn, lane, 1);               // X over e tile
    __syncthreads();
    ZERO_C(C);
    gemm_T4s(smf, sb, wM1, C, tid, wm, wn, lane, pl4);   // MLP layer 1
    gelu_ln_ep(C, smf, wm, wn, lane, F_PAR + 384, F_PAR + 512, F_PAR + 640);

    // epilogue: residual (recomputed l0 / re-read l1), store e (l0), RED4 scatter
    const float* w0 = smf + F_PAR + 768;
    const float* w1 = smf + F_PAR + 896;
    const float* bb = smf + F_PAR + 1024;
#pragma unroll
    for (int mm = 0; mm < 2; mm++)
#pragma unroll
        for (int hx = 0; hx < 2; hx++) {
            int row = wm * 32 + mm * 16 + hx * 8 + g;
            float ex0 = 0.f, ex1 = 0.f;
            if (layer0) {
                float2 xy = *(const float2*)(edges + 2 * (size_t)(base + row));
                ex0 = xy.x; ex1 = xy.y;
            }
            float* eo = e + (size_t)(base + row) * DM;
            float v[8];
#pragma unroll
            for (int nt = 0; nt < 4; nt++) {
                int col = wn * 32 + nt * 8 + q * 2;
                float r0v, r1v;
                if (layer0) {
                    r0v = fmaf(ex0, w0[col], fmaf(ex1, w1[col], bb[col]));
                    r1v = fmaf(ex0, w0[col + 1], fmaf(ex1, w1[col + 1], bb[col + 1]));
                } else {
                    float2 er = *(const float2*)(eo + col);
                    r0v = er.x; r1v = er.y;
                }
                float v0 = C[mm][nt][hx * 2 + 0] + r0v;
                float v1 = C[mm][nt][hx * 2 + 1] + r1v;
                if (layer0) *(float2*)(eo + col) = make_float2(v0, v1);
                v[nt * 2] = v0; v[nt * 2 + 1] = v1;
            }
            // permuted agg scatter: thread's 8 values are contiguous
            float* ag = agg + (size_t)rIdx[mm][hx] * DM + wn * 32 + q * 8;
            float4 f0, f1;
            f0.x = v[0]; f0.y = v[1]; f0.z = v[2]; f0.w = v[3];
            f1.x = v[4]; f1.y = v[5]; f1.z = v[6]; f1.w = v[7];
            RED4(ag, f0);
            RED4(ag + 4, f1);
        }
}

// ---------------- node kernel (64 nodes per CTA) --------------------------------
__global__ __launch_bounds__(256, 3) void node_k(
    float* __restrict__ h, const float* __restrict__ agg,
    const float* __restrict__ cnt,
    const float* __restrict__ wN0, const float* __restrict__ bn0c,
    const float* __restrict__ g0, const float* __restrict__ be0,
    const float* __restrict__ wM1, const float* __restrict__ b1,
    const float* __restrict__ g1, const float* __restrict__ be1,
    float* __restrict__ hs0, float* __restrict__ hr0,
    const float* __restrict__ wS0, const float* __restrict__ wR0, int tail,
    const float* __restrict__ wO, const float* __restrict__ ob,
    const float* __restrict__ og, const float* __restrict__ obb,
    const float* __restrict__ pw, const float* __restrict__ pb,
    float* __restrict__ outp, int do_out)
{
    extern __shared__ float smf[];
    uint32_t sb = smem_u32(smf);
    int tid = threadIdx.x, lane = tid & 31, wid = tid >> 5;
    int wm = wid >> 2, wn = wid & 3;
    int g = lane >> 2, q = lane & 3;
    int pl4 = (g * 4 + (q ^ fAg(g))) << 2;
    int base = blockIdx.x * 64;
    int r = tid >> 2, q4 = tid & 3;
    if (tid < 64) {
        int n = min(base + tid, NNODES - 1);
        smf[tid] = 1.0f / fmaxf(cnt[n], 1.0f);
    }
    if (tid < 128) {
        float* p = smf + F_PAR;
        p[tid] = bn0c[tid];      p[128 + tid] = g0[tid];
        p[256 + tid] = be0[tid]; p[384 + tid] = b1[tid];
        p[512 + tid] = g1[tid];  p[640 + tid] = be1[tid];
        if (do_out) {
            p[768 + tid]  = ob[tid];
            p[896 + tid]  = og[tid];
            p[1024 + tid] = obb[tid];
        }
    }
    int nr = min(base + r, NNODES - 1);
    stage_E32(smf + F_T + q4 * 2048, h + (size_t)nr * DM + q4 * 32, r);

    // GEMM1: K=256, agg chunks (PERMUTED) staged in-place into consumed T slots
    float C[2][4][4];
    ZERO_C(C);
    copy_w_async(sb + F_W * 4, wN0, tid); CP_COMMIT();
    CP_WAIT0(); __syncthreads();
#pragma unroll 1
    for (int c = 0; c < 8; c++) {
        if (c < 7) {
            int cn = c + 1;
            copy_w_async(sb + F_W * 4 + (cn & 1) * 16384, wN0 + cn * 4096, tid);
            CP_COMMIT();
            if (cn >= 4)
                stage_Agg_perm(smf + F_T + (cn & 3) * 2048,
                               agg + (size_t)nr * DM + ((cn & 3) << 5) + q4 * 8,
                               r, q4, smf[r]);
        }
        chunk_mma(smf + F_T + (c & 3) * 2048, smf + F_W + (c & 1) * 4096,
                  C, wm, wn, lane, pl4);
        CP_WAIT0();
        __syncthreads();
    }
    gelu_ln_ep(C, smf, wm, wn, lane, F_PAR, F_PAR + 128, F_PAR + 256);
    write_T(C, smf, F_T, wm, wn, lane, 1);
    __syncthreads();
    ZERO_C(C);
    gemm_T4s(smf, sb, wM1, C, tid, wm, wn, lane, pl4);   // MLP layer 1
    gelu_ln_ep(C, smf, wm, wn, lane, F_PAR + 384, F_PAR + 512, F_PAR + 640);

    // epilogue: h_new = C + h; store h unless final layer; keep h_new in C
#pragma unroll
    for (int mm = 0; mm < 2; mm++)
#pragma unroll
        for (int hx = 0; hx < 2; hx++) {
            int row = wm * 32 + mm * 16 + hx * 8 + g;
            if (base + row >= NNODES) continue;
            float* ho = h + (size_t)(base + row) * DM;
#pragma unroll
            for (int nt = 0; nt < 4; nt++) {
                int col = wn * 32 + nt * 8 + q * 2;
                float2 hv = *(const float2*)(ho + col);
                float v0 = C[mm][nt][hx * 2 + 0] + hv.x;
                float v1 = C[mm][nt][hx * 2 + 1] + hv.y;
                if (!do_out) *(float2*)(ho + col) = make_float2(v0, v1);
                C[mm][nt][hx * 2 + 0] = v0;
                C[mm][nt][hx * 2 + 1] = v1;
            }
        }

    if (tail) {
        __syncthreads();
        write_T(C, smf, F_T, wm, wn, lane, 1);     // X = tf32(h_new)
        __syncthreads();
        ZERO_C(C);
        gemm_T4s(smf, sb, wS0, C, tid, wm, wn, lane, pl4);
        store_perm(C, hs0, base, wm, wn, g, q);
        ZERO_C(C);
        gemm_T4s(smf, sb, wR0, C, tid, wm, wn, lane, pl4);
        store_perm(C, hr0, base, wm, wn, g, q);
    }
    if (do_out) {
        __syncthreads();
        write_T(C, smf, F_T, wm, wn, lane, 0);     // exact h_new
        __syncthreads();
        ZERO_C(C);
        gemm_T4s(smf, sb, wO, C, tid, wm, wn, lane, pl4);
        gelu_ln_ep(C, smf, wm, wn, lane, F_PAR + 768, F_PAR + 896, F_PAR + 1024);
        write_T(C, smf, F_T, wm, wn, lane, 0);
        float* sPw = smf + F_W;
        for (int i = tid; i < 128 * PREDL; i += 256) sPw[i] = pw[i];
        if (tid < PREDL) smf[F_W + 128 * PREDL + tid] = pb[tid];
        __syncthreads();
        if (base + r < NNODES) {
            ROWBASE(r, rb, fg);
            float acc[6];
#pragma unroll
            for (int j = 0; j < 6; j++)
                acc[j] = smf[F_W + 128 * PREDL + q4 * 6 + j];
#pragma unroll 1
            for (int ch = 0; ch < 4; ch++) {
                const float* X = smf + F_T + ch * 2048;
#pragma unroll
                for (int j = 0; j < 32; j++) {
                    float xv = X[AFIDX(rb, fg, j)];
                    const float* pr = sPw + (ch * 32 + j) * PREDL + q4 * 6;
#pragma unroll
                    for (int o = 0; o < 6; o++) acc[o] = fmaf(xv, pr[o], acc[o]);
                }
            }
            float* op = outp + (size_t)(base + r) * PREDL + q4 * 6;
#pragma unroll
            for (int j = 0; j < 6; j++) op[j] = acc[j];
        }
    }
}

// ---------------- node embedding (+ permuted hs0/hr0 for layer 0) ---------------
__global__ __launch_bounds__(256, 3) void emb_k(
    const float* __restrict__ nodes, const float* __restrict__ wE,
    const float* __restrict__ bias, float* __restrict__ h,
    float* __restrict__ hs0, float* __restrict__ hr0,
    const float* __restrict__ wS0, const float* __restrict__ wR0)
{
    extern __shared__ float smf[];
    uint32_t sb = smem_u32(smf);
    int tid = threadIdx.x, lane = tid & 31, wid = tid >> 5;
    int wm = wid >> 2, wn = wid & 3;
    int g = lane >> 2, q = lane & 3;
    int pl4 = (g * 4 + (q ^ fAg(g))) << 2;
    int base = blockIdx.x * 64;
    int r = tid >> 2, q4 = tid & 3;
    if (tid < 128) smf[F_PAR + tid] = bias[tid];
    int nr = min(base + r, NNODES - 1);
    const float* src = nodes + (size_t)nr * 288;

    // streamed GEMM over K=288: A streams through T[0]/T[1]
    float C[2][4][4];
    ZERO_C(C);
    copy_w_async(sb + F_W * 4, wE, tid); CP_COMMIT();
    stage_Af8(smf + F_T, src + q4 * 8, r, q4);
    CP_WAIT0(); __syncthreads();
#pragma unroll 1
    for (int c = 0; c < 9; c++) {
        if (c < 8) {
            int cn = c + 1;
            copy_w_async(sb + F_W * 4 + (cn & 1) * 16384, wE + cn * 4096, tid);
            CP_COMMIT();
            stage_Af8(smf + F_T + (cn & 1) * 2048, src + cn * 32 + q4 * 8, r, q4);
        }
        chunk_mma(smf + F_T + (c & 1) * 2048, smf + F_W + (c & 1) * 4096,
                  C, wm, wn, lane, pl4);
        CP_WAIT0();
        __syncthreads();
    }
    // h = C + bias (direct store), keep h in C for tails
#pragma unroll
    for (int mm = 0; mm < 2; mm++)
#pragma unroll
        for (int hx = 0; hx < 2; hx++) {
            int row = wm * 32 + mm * 16 + hx * 8 + g;
            float* ho = h + (size_t)(base + row) * DM;
#pragma unroll
            for (int nt = 0; nt < 4; nt++) {
                int col = wn * 32 + nt * 8 + q * 2;
                float v0 = C[mm][nt][hx * 2 + 0] + smf[F_PAR + col];
                float v1 = C[mm][nt][hx * 2 + 1] + smf[F_PAR + col + 1];
                if (base + row < NNODES)
                    *(float2*)(ho + col) = make_float2(v0, v1);
                C[mm][nt][hx * 2 + 0] = v0;
                C[mm][nt][hx * 2 + 1] = v1;
            }
        }
    write_T(C, smf, F_T, wm, wn, lane, 1);    // X = tf32(h)
    __syncthreads();
    ZERO_C(C);
    gemm_T4s(smf, sb, wS0, C, tid, wm, wn, lane, pl4);
    store_perm(C, hs0, base, wm, wn, g, q);
    ZERO_C(C);
    gemm_T4s(smf, sb, wR0, C, tid, wm, wn, lane, pl4);
    store_perm(C, hr0, base, wm, wn, g, q);
}

// ---------------- launch ------------------------------------------------------
extern "C" void kernel_launch(void* const* d_in, const int* in_sizes, int n_in,
                              void* d_out, int out_size)
{
    const float* nodes        = (const float*)d_in[0];
    const float* edges        = (const float*)d_in[1];
    const int*   senders      = (const int*)d_in[2];
    const int*   receivers    = (const int*)d_in[3];
    const float* w_node_emb   = (const float*)d_in[4];
    const float* b_node_emb   = (const float*)d_in[5];
    const float* w_edge_emb   = (const float*)d_in[6];
    const float* b_edge_emb   = (const float*)d_in[7];
    const float* edge_proj_w  = (const float*)d_in[8];
    const float* edge_proj_b  = (const float*)d_in[9];
    const float* node_proj_w  = (const float*)d_in[10];
    const float* node_proj_b  = (const float*)d_in[11];
    const float* edge_mlp_w   = (const float*)d_in[12];
    const float* edge_mlp_b   = (const float*)d_in[13];
    const float* edge_ln_g    = (const float*)d_in[14];
    const float* edge_ln_b    = (const float*)d_in[15];
    const float* node_mlp_w   = (const float*)d_in[16];
    const float* node_mlp_b   = (const float*)d_in[17];
    const float* node_ln_g    = (const float*)d_in[18];
    const float* node_ln_b    = (const float*)d_in[19];
    const float* mlp_out_w    = (const float*)d_in[20];
    const float* mlp_out_b    = (const float*)d_in[21];
    const float* mlp_out_g    = (const float*)d_in[22];
    const float* mlp_out_beta = (const float*)d_in[23];
    const float* proj_w       = (const float*)d_in[24];
    const float* proj_b       = (const float*)d_in[25];
    float* out = (float*)d_out;

    float *h, *e, *agg, *cnt, *wt, *hs, *hr, *cw;
    cudaGetSymbolAddress((void**)&h,   g_h);
    cudaGetSymbolAddress((void**)&e,   g_e);
    cudaGetSymbolAddress((void**)&agg, g_agg);
    cudaGetSymbolAddress((void**)&cnt, g_cnt);
    cudaGetSymbolAddress((void**)&wt,  g_wt);
    cudaGetSymbolAddress((void**)&hs,  g_hs);
    cudaGetSymbolAddress((void**)&hr,  g_hr);
    cudaGetSymbolAddress((void**)&cw,  g_cw);

    cudaFuncSetAttribute(edge_k, cudaFuncAttributeMaxDynamicSharedMemorySize, SMEMB);
    cudaFuncSetAttribute(node_k, cudaFuncAttributeMaxDynamicSharedMemorySize, SMEMB);
    cudaFuncSetAttribute(emb_k,  cudaFuncAttributeMaxDynamicSharedMemorySize, SMEMB);

    int nblk = (NNODES + 63) / 64;  // 313

    compose_k<<<1284, 128>>>(edge_proj_w, edge_proj_b, edge_mlp_w, edge_mlp_b,
                             node_proj_w, node_proj_b, node_mlp_w, node_mlp_b, cw);
    prep_frag<<<148, 256>>>(cw, edge_mlp_w, node_mlp_w, mlp_out_w, w_node_emb,
                            wt, cnt);
    init_k<<<2500 + (NEDGES + 255) / 256, 256>>>((float4*)agg, receivers, cnt, 1);
    emb_k<<<nblk, 256, SMEMB>>>(nodes, wt + W_EMB * 4096, b_node_emb, h,
                                hs, hr, wt + W_S0(0) * 4096, wt + W_R0(0) * 4096);
    for (int l = 0; l < 2; l++) {
        edge_k<<<NEDGES / 64, 256, SMEMB>>>(
            e, edges, senders, receivers, hs, hr,
            w_edge_emb, b_edge_emb,
            wt + W_E0(l) * 4096, cw + l * CWL + 81920,
            edge_ln_g + (l * 2 + 0) * 128, edge_ln_b + (l * 2 + 0) * 128,
            wt + W_M1E(l) * 4096, edge_mlp_b + (l * 2 + 1) * 128,
            edge_ln_g + (l * 2 + 1) * 128, edge_ln_b + (l * 2 + 1) * 128,
            agg, l == 0);
        node_k<<<nblk, 256, SMEMB>>>(
            h, agg, cnt,
            wt + W_N0(l) * 4096, cw + l * CWL + 82048,
            node_ln_g + (l * 2 + 0) * 128, node_ln_b + (l * 2 + 0) * 128,
            wt + W_M1N(l) * 4096, node_mlp_b + (l * 2 + 1) * 128,
            node_ln_g + (l * 2 + 1) * 128, node_ln_b + (l * 2 + 1) * 128,
            hs, hr, wt + W_S0(1) * 4096, wt + W_R0(1) * 4096, l == 0,
            wt + W_OUT * 4096, mlp_out_b, mlp_out_g, mlp_out_beta,
            proj_w, proj_b, out, l == 1);
        if (l == 0) init_k<<<2500, 256>>>((float4*)agg, receivers, cnt, 0);
    }
}

// round 15
// speedup vs baseline: 1.5028x; 1.5028x over previous
#include <cuda_runtime.h>
#include <cstdint>

#define NNODES 20000
#define NEDGES 320000
#define DM 128
#define PREDL 24

// ---------------- device scratch ----------------------------------------------
__device__ float g_h[NNODES * DM];
__device__ float g_e[(size_t)NEDGES * DM];
__device__ float g_agg[NNODES * DM];
__device__ float g_cnt[NNODES];
__device__ float g_hs[NNODES * DM];     // (h @ Ws0) permuted
__device__ float g_hr[NNODES * DM];     // (h @ Wr0) permuted
#define CWL 82176
__device__ float g_cw[2 * CWL];         // composed weights (fp32)
__device__ float g_wt[69 * 4096];       // fragment-layout weights (tf32)

// g_wt chunk offsets
#define W_E0(l)  ((l) * 4)
#define W_M1E(l) (8 + (l) * 4)
#define W_N0(l)  (16 + (l) * 8)
#define W_M1N(l) (32 + (l) * 4)
#define W_S0(l)  (40 + (l) * 8)
#define W_R0(l)  (44 + (l) * 8)
#define W_OUT    56
#define W_EMB    60

// ---------------- smem float offsets (M=64 tile) --------------------------------
#define F_SUM 128               // 256
#define F_SQ  384               // 256
#define F_PAR 640               // 1152 params
#define F_W   1792              // 2 x 4096 W double buffer
#define F_T   (F_W + 8192)      // 4 x 2048 activation tile
#define SMEMB ((F_T + 8192) * 4)   // 72704 B -> 3 CTAs/SM

// ---------------- helpers ------------------------------------------------------
__device__ __forceinline__ uint32_t tfr(float x) {
    uint32_t r;
    asm("cvt.rna.tf32.f32 %0, %1;" : "=r"(r) : "f"(x));
    return r;
}
__device__ __forceinline__ float tff(float x) { return __uint_as_float(tfr(x)); }

__device__ __forceinline__ uint32_t smem_u32(const void* p) {
    uint32_t a;
    asm("{ .reg .u64 t; cvta.to.shared.u64 t, %1; cvt.u32.u64 %0, t; }"
        : "=r"(a) : "l"(p));
    return a;
}

__device__ __forceinline__ void mma8(float c[4], uint32_t a0, uint32_t a1,
                                     uint32_t a2, uint32_t a3,
                                     uint32_t b0, uint32_t b1) {
    asm volatile(
        "mma.sync.aligned.m16n8k8.row.col.f32.tf32.tf32.f32 "
        "{%0,%1,%2,%3}, {%4,%5,%6,%7}, {%8,%9}, {%0,%1,%2,%3};"
        : "+f"(c[0]), "+f"(c[1]), "+f"(c[2]), "+f"(c[3])
        : "r"(a0), "r"(a1), "r"(a2), "r"(a3), "r"(b0), "r"(b1));
}

// HW tanh (MUFU, sm_75+)
__device__ __forceinline__ float tanh_hw(float x) {
    float r;
    asm("tanh.approx.f32 %0, %1;" : "=f"(r) : "f"(x));
    return r;
}
__device__ __forceinline__ float geluf(float x) {
    float x3 = x * x * x;
    return 0.5f * x * (1.0f + tanh_hw(fmaf(0.044715f * 0.7978845608028654f, x3,
                                           0.7978845608028654f * x)));
}

__device__ __forceinline__ int fAg(int g) { return (g ^ (g >> 2)) & 3; }

// A-fragment index in a 2048-float chunk (64 rows x 32 k)
__device__ __forceinline__ int aidx(int row, int kl) {
    int wm = row >> 5, mm = (row >> 4) & 1, r8 = (row >> 3) & 1, g = row & 7;
    int kk = kl >> 3, k4 = (kl >> 2) & 1, tig = kl & 3;
    return (((kk * 2 + wm) * 2 + mm) << 7) + ((g * 4 + (tig ^ fAg(g))) << 2)
           + r8 + (k4 << 1);
}
// B-fragment index in a 4096-float chunk
__device__ __forceinline__ int bidx(int kl, int n) {
    int kk = kl >> 3, k4 = (kl >> 2) & 1, tig = kl & 3;
    int wn = n >> 5, ntp = (n >> 4) & 1, ntb = (n >> 3) & 1, gq = n & 7;
    return (((kk * 4 + wn) * 2 + ntp) << 7) + ((gq * 4 + tig) << 2)
           + ntb * 2 + k4;
}

#define CP16(daddr, src) asm volatile( \
    "cp.async.cg.shared.global [%0], [%1], 16;" :: "r"(daddr), "l"(src))
#define CP_COMMIT() asm volatile("cp.async.commit_group;" ::: "memory")
#define CP_WAIT0()  asm volatile("cp.async.wait_group 0;" ::: "memory")

// one 4096-float W chunk via cp.async (256 threads x 4 x 16B)
__device__ __forceinline__ void copy_w_async(uint32_t dsts,
                                             const float* __restrict__ src,
                                             int tid) {
    CP16(dsts + tid * 16, src + tid * 4);
    CP16(dsts + (tid + 256) * 16, src + (tid + 256) * 4);
    CP16(dsts + (tid + 512) * 16, src + (tid + 512) * 4);
    CP16(dsts + (tid + 768) * 16, src + (tid + 768) * 4);
}

// one 32-wide K chunk; warp covers 32 rows x 32 cols (A chunk = 2048 floats)
__device__ __forceinline__ void chunk_mma(const float* __restrict__ sA,
                                          const float* __restrict__ sW,
                                          float C[2][4][4], int wm, int wn,
                                          int lane, int pl4) {
#pragma unroll
    for (int kk = 0; kk < 4; kk++) {
        float4 b0 = *(const float4*)(sW + (((kk * 4 + wn) * 2 + 0) << 7)
                                     + (lane << 2));
        float4 b1 = *(const float4*)(sW + (((kk * 4 + wn) * 2 + 1) << 7)
                                     + (lane << 2));
#pragma unroll
        for (int mm = 0; mm < 2; mm++) {
            float4 av = *(const float4*)(sA + (((kk * 2 + wm) * 2 + mm) << 7) + pl4);
            uint32_t a0 = __float_as_uint(av.x), a1 = __float_as_uint(av.y);
            uint32_t a2 = __float_as_uint(av.z), a3 = __float_as_uint(av.w);
            mma8(C[mm][0], a0, a1, a2, a3,
                 __float_as_uint(b0.x), __float_as_uint(b0.y));
            mma8(C[mm][1], a0, a1, a2, a3,
                 __float_as_uint(b0.z), __float_as_uint(b0.w));
            mma8(C[mm][2], a0, a1, a2, a3,
                 __float_as_uint(b1.x), __float_as_uint(b1.y));
            mma8(C[mm][3], a0, a1, a2, a3,
                 __float_as_uint(b1.z), __float_as_uint(b1.w));
        }
    }
}

__device__ __forceinline__ void stage_Af8(float* chunk, const float* __restrict__ src,
                                          int r, int q4) {
    float4 v0 = *(const float4*)(src);
    float4 v1 = *(const float4*)(src + 4);
    chunk[aidx(r, q4 * 8 + 0)] = tff(v0.x);
    chunk[aidx(r, q4 * 8 + 1)] = tff(v0.y);
    chunk[aidx(r, q4 * 8 + 2)] = tff(v0.z);
    chunk[aidx(r, q4 * 8 + 3)] = tff(v0.w);
    chunk[aidx(r, q4 * 8 + 4)] = tff(v1.x);
    chunk[aidx(r, q4 * 8 + 5)] = tff(v1.y);
    chunk[aidx(r, q4 * 8 + 6)] = tff(v1.z);
    chunk[aidx(r, q4 * 8 + 7)] = tff(v1.w);
}
__device__ __forceinline__ void stage_Af8s(float* chunk, const float* __restrict__ src,
                                           int r, int q4, float sc) {
    float4 v0 = *(const float4*)(src);
    float4 v1 = *(const float4*)(src + 4);
    chunk[aidx(r, q4 * 8 + 0)] = tff(v0.x * sc);
    chunk[aidx(r, q4 * 8 + 1)] = tff(v0.y * sc);
    chunk[aidx(r, q4 * 8 + 2)] = tff(v0.z * sc);
    chunk[aidx(r, q4 * 8 + 3)] = tff(v0.w * sc);
    chunk[aidx(r, q4 * 8 + 4)] = tff(v1.x * sc);
    chunk[aidx(r, q4 * 8 + 5)] = tff(v1.y * sc);
    chunk[aidx(r, q4 * 8 + 6)] = tff(v1.z * sc);
    chunk[aidx(r, q4 * 8 + 7)] = tff(v1.w * sc);
}

// stage 32 cols of a row EXACT into A-frag chunk
__device__ __forceinline__ void stage_E32(float* chunk, const float* __restrict__ src,
                                          int r) {
#pragma unroll
    for (int i = 0; i < 8; i++) {
        float4 v = *(const float4*)(src + i * 4);
        chunk[aidx(r, i * 4 + 0)] = v.x;
        chunk[aidx(r, i * 4 + 1)] = v.y;
        chunk[aidx(r, i * 4 + 2)] = v.z;
        chunk[aidx(r, i * 4 + 3)] = v.w;
    }
}

__device__ __forceinline__ void write_T(float C[2][4][4], float* smf, int fbase,
                                        int wm, int wn, int lane, int cvt) {
    int g = lane >> 2, q = lane & 3;
#pragma unroll
    for (int mm = 0; mm < 2; mm++)
#pragma unroll
        for (int hx = 0; hx < 2; hx++) {
            int row = wm * 32 + mm * 16 + hx * 8 + g;
#pragma unroll
            for (int nt = 0; nt < 4; nt++)
#pragma unroll
                for (int s = 0; s < 2; s++) {
                    int col = wn * 32 + nt * 8 + q * 2 + s;
                    float v = C[mm][nt][hx * 2 + s];
                    smf[fbase + (col >> 5) * 2048 + aidx(row, col & 31)] =
                        cvt ? tff(v) : v;
                }
        }
}

__device__ __forceinline__ void gelu_ln_ep(float C[2][4][4], float* smf,
                                           int wm, int wn, int lane,
                                           int pb, int pg, int pbe) {
    int g = lane >> 2, q = lane & 3;
    float* sSum = smf + F_SUM;
    float* sSq  = smf + F_SQ;
#pragma unroll
    for (int mm = 0; mm < 2; mm++)
#pragma unroll
        for (int hx = 0; hx < 2; hx++) {
            float ps = 0.f, pq = 0.f;
#pragma unroll
            for (int nt = 0; nt < 4; nt++)
#pragma unroll
                for (int s = 0; s < 2; s++) {
                    int col = wn * 32 + nt * 8 + q * 2 + s;
                    float v = geluf(C[mm][nt][hx * 2 + s] + smf[pb + col]);
                    C[mm][nt][hx * 2 + s] = v;
                    ps += v; pq += v * v;
                }
            ps += __shfl_xor_sync(0xffffffffu, ps, 1);
            ps += __shfl_xor_sync(0xffffffffu, ps, 2);
            pq += __shfl_xor_sync(0xffffffffu, pq, 1);
            pq += __shfl_xor_sync(0xffffffffu, pq, 2);
            if (q == 0) {
                int row = wm * 32 + mm * 16 + hx * 8 + g;
                sSum[row * 4 + wn] = ps;
                sSq[row * 4 + wn]  = pq;
            }
        }
    __syncthreads();
#pragma unroll
    for (int mm = 0; mm < 2; mm++)
#pragma unroll
        for (int hx = 0; hx < 2; hx++) {
            int row = wm * 32 + mm * 16 + hx * 8 + g;
            float m = (sSum[row * 4] + sSum[row * 4 + 1]
                       + sSum[row * 4 + 2] + sSum[row * 4 + 3]) * (1.0f / 128.0f);
            float qv = (sSq[row * 4] + sSq[row * 4 + 1]
                        + sSq[row * 4 + 2] + sSq[row * 4 + 3]) * (1.0f / 128.0f);
            float rs = rsqrtf(qv - m * m + 1e-5f);
#pragma unroll
            for (int nt = 0; nt < 4; nt++)
#pragma unroll
                for (int s = 0; s < 2; s++) {
                    int col = wn * 32 + nt * 8 + q * 2 + s;
                    C[mm][nt][hx * 2 + s] =
                        (C[mm][nt][hx * 2 + s] - m) * rs * smf[pg + col] + smf[pbe + col];
                }
        }
}

#define ZERO_C(C) do { \
    _Pragma("unroll") for (int _m = 0; _m < 2; _m++) \
    _Pragma("unroll") for (int _n = 0; _n < 4; _n++) \
    _Pragma("unroll") for (int _s = 0; _s < 4; _s++) (C)[_m][_n][_s] = 0.f; } while (0)

// streamed K=128 GEMM: A resident in T chunks, W double-buffered
__device__ __forceinline__ void gemm_T4s(float* smf, uint32_t sb,
                                         const float* __restrict__ W,
                                         float C[2][4][4], int tid,
                                         int wm, int wn, int lane, int pl4) {
    copy_w_async(sb + F_W * 4, W, tid); CP_COMMIT();
    CP_WAIT0(); __syncthreads();
#pragma unroll 1
    for (int c = 0; c < 4; c++) {
        if (c < 3) {
            copy_w_async(sb + F_W * 4 + ((c + 1) & 1) * 16384, W + (c + 1) * 4096, tid);
            CP_COMMIT();
        }
        chunk_mma(smf + F_T + c * 2048, smf + F_W + (c & 1) * 4096,
                  C, wm, wn, lane, pl4);
        CP_WAIT0();
        __syncthreads();
    }
}

#define ROWBASE(r, rb, fg) \
    int rb = (((r) >> 5) * 2 + (((r) >> 4) & 1)) * 128 + ((r) & 7) * 16 \
             + (((r) >> 3) & 1); \
    int fg = fAg((r) & 7)
#define AFIDX(rb, fg, j) \
    (((j) >> 3) * 512 + (rb) + ((((j) & 3) ^ (fg)) << 2) + ((((j) >> 2) & 1) << 1))

#define RED2(p, a, b) asm volatile( \
    "red.global.add.v2.f32 [%0], {%1,%2};" :: "l"(p), "f"(a), "f"(b) : "memory")

// direct permuted store of C fragments to gout (matches edge gather layout)
__device__ __forceinline__ void store_perm(const float C[2][4][4],
                                           float* __restrict__ gout, int base,
                                           int wm, int wn, int g, int q) {
#pragma unroll
    for (int mm = 0; mm < 2; mm++)
#pragma unroll
        for (int hx = 0; hx < 2; hx++) {
            int row = wm * 32 + mm * 16 + hx * 8 + g;
            if (base + row >= NNODES) continue;
            float* go = gout + (size_t)(base + row) * DM + wn * 32 + q * 8;
            float4 f0, f1;
            f0.x = C[mm][0][hx * 2 + 0]; f0.y = C[mm][0][hx * 2 + 1];
            f0.z = C[mm][1][hx * 2 + 0]; f0.w = C[mm][1][hx * 2 + 1];
            f1.x = C[mm][2][hx * 2 + 0]; f1.y = C[mm][2][hx * 2 + 1];
            f1.z = C[mm][3][hx * 2 + 0]; f1.w = C[mm][3][hx * 2 + 1];
            *(float4*)go = f0;
            *(float4*)(go + 4) = f1;
        }
}

// ---------------- compose: fp32 weight products --------------------------------
__global__ void compose_k(const float* __restrict__ epw, const float* __restrict__ epb,
                          const float* __restrict__ emw, const float* __restrict__ emb_b,
                          const float* __restrict__ npw, const float* __restrict__ npb,
                          const float* __restrict__ nmw, const float* __restrict__ nmb,
                          float* __restrict__ cw) {
    int bi = blockIdx.x, j = threadIdx.x;
    int l = bi / 642, rr = bi % 642;
    const float *A, *B;
    float* out;
    float extra = 0.f;
    if (rr < 384) {
        A = epw + (size_t)l * 384 * 128 + rr * 128;
        B = emw + (l * 2) * 16384;
        out = cw + l * CWL + rr * 128;
    } else if (rr < 640) {
        int r2 = rr - 384;
        A = npw + (size_t)l * 256 * 128 + r2 * 128;
        B = nmw + (l * 2) * 16384;
        out = cw + l * CWL + 49152 + r2 * 128;
    } else if (rr == 640) {
        A = epb + l * 128; B = emw + (l * 2) * 16384;
        out = cw + l * CWL + 81920;
        extra = emb_b[(l * 2) * 128 + j];
    } else {
        A = npb + l * 128; B = nmw + (l * 2) * 16384;
        out = cw + l * CWL + 82048;
        extra = nmb[(l * 2) * 128 + j];
    }
    float acc = extra;
    for (int k = 0; k < 128; k++) acc += A[k] * B[k * 128 + j];
    out[j] = acc;
}

// ---------------- prep: all weights -> B-frag chunks; zero cnt -----------------
__global__ void prep_frag(const float* __restrict__ cw,
                          const float* __restrict__ emw,
                          const float* __restrict__ nmw,
                          const float* __restrict__ mow,
                          const float* __restrict__ wemb,
                          float* __restrict__ wt, float* __restrict__ cnt) {
    int b = blockIdx.x, tid = threadIdx.x;
    if (b < 69) {
        const float* M; int c;
        if (b < 8)       { int l = b >> 2; c = b & 3; M = cw + l * CWL; }
        else if (b < 16) { int l = (b - 8) >> 2; c = (b - 8) & 3;
                           M = emw + (l * 2 + 1) * 16384; }
        else if (b < 32) { int l = (b - 16) >> 3; c = (b - 16) & 7;
                           M = cw + l * CWL + 49152; }
        else if (b < 40) { int l = (b - 32) >> 2; c = (b - 32) & 3;
                           M = nmw + (l * 2 + 1) * 16384; }
        else if (b < 56) { int l = (b - 40) >> 3; int s = (b - 40) & 7;
                           c = s & 3; M = cw + l * CWL + 16384 + (s >> 2) * 16384; }
        else if (b < 60) { c = b - 56; M = mow; }
        else             { c = b - 60; M = wemb; }
        int kl = tid >> 3, n0 = (tid & 7) * 16;
#pragma unroll
        for (int j = 0; j < 16; j++) {
            int n = n0 + j;
            wt[b * 4096 + bidx(kl, n)] = tff(M[(c * 32 + kl) * 128 + n]);
        }
    } else {
        int i = (b - 69) * 256 + tid;
        if (i < NNODES) cnt[i] = 0.f;
    }
}

// merged: zero agg (first 2500 blocks) + in-degree count (rest)
__global__ void init_k(float4* __restrict__ agg4, const int* __restrict__ rcv,
                       float* __restrict__ cnt) {
    int b = blockIdx.x;
    if (b < 2500) {
        int i = b * 256 + threadIdx.x;
        if (i < NNODES * 32) agg4[i] = make_float4(0.f, 0.f, 0.f, 0.f);
    } else {
        int i = (b - 2500) * 256 + threadIdx.x;
        if (i < NEDGES) atomicAdd(cnt + rcv[i], 1.0f);
    }
}

// ---------------- edge kernel (64 edges per CTA) --------------------------------
__global__ __launch_bounds__(256, 3) void edge_k(
    float* __restrict__ e, const float* __restrict__ edges,
    const int* __restrict__ snd, const int* __restrict__ rcv,
    const float* __restrict__ hs0, const float* __restrict__ hr0,
    const float* __restrict__ wem, const float* __restrict__ bem,
    const float* __restrict__ wE0, const float* __restrict__ b0c,
    const float* __restrict__ g0, const float* __restrict__ be0,
    const float* __restrict__ wM1, const float* __restrict__ b1,
    const float* __restrict__ g1, const float* __restrict__ be1,
    float* __restrict__ agg, int layer0)
{
    extern __shared__ float smf[];
    uint32_t sb = smem_u32(smf);
    int tid = threadIdx.x, lane = tid & 31, wid = tid >> 5;
    int wm = wid >> 2, wn = wid & 3;
    int g = lane >> 2, q = lane & 3;
    int pl4 = (g * 4 + (q ^ fAg(g))) << 2;
    int base = blockIdx.x * 64;
    int r = tid >> 2, q4 = tid & 3;
    int* sI = (int*)smf;
    if (tid < 64)        sI[tid] = snd[base + tid];
    else if (tid < 128)  sI[tid] = rcv[base + tid - 64];
    if (tid < 128) {
        float* p = smf + F_PAR;
        p[tid] = b0c[tid];       p[128 + tid] = g0[tid];
        p[256 + tid] = be0[tid]; p[384 + tid] = b1[tid];
        p[512 + tid] = g1[tid];  p[640 + tid] = be1[tid];
        if (layer0) {
            p[768 + tid]  = wem[tid];
            p[896 + tid]  = wem[128 + tid];
            p[1024 + tid] = bem[tid];
        }
    }
    if (layer0) {
        __syncthreads();   // wem/bem visible
        float2 xy = *(const float2*)(edges + 2 * (size_t)(base + r));
        const float* w0 = smf + F_PAR + 768;
        const float* w1 = smf + F_PAR + 896;
        const float* bb = smf + F_PAR + 1024;
        float* Tc = smf + F_T + q4 * 2048;
#pragma unroll
        for (int i = 0; i < 32; i++) {
            int col = q4 * 32 + i;
            Tc[aidx(r, i)] =
                tff(fmaf(xy.x, w0[col], fmaf(xy.y, w1[col], bb[col])));
        }
    } else {
        stage_E32(smf + F_T + q4 * 2048,
                  e + (size_t)(base + r) * DM + q4 * 32, r);
    }
    __syncthreads();

    // C init = gathered hs0p + hr0p (permuted layout, coalesced 32B)
    float C[2][4][4];
#pragma unroll
    for (int mm = 0; mm < 2; mm++)
#pragma unroll
        for (int hx = 0; hx < 2; hx++) {
            int row = wm * 32 + mm * 16 + hx * 8 + g;
            const float4* hp = (const float4*)(hs0 + (size_t)sI[row] * DM
                                               + wn * 32 + q * 8);
            const float4* rp = (const float4*)(hr0 + (size_t)sI[64 + row] * DM
                                               + wn * 32 + q * 8);
            float4 a0 = hp[0], a1 = hp[1], c0 = rp[0], c1 = rp[1];
            C[mm][0][hx * 2 + 0] = a0.x + c0.x;
            C[mm][0][hx * 2 + 1] = a0.y + c0.y;
            C[mm][1][hx * 2 + 0] = a0.z + c0.z;
            C[mm][1][hx * 2 + 1] = a0.w + c0.w;
            C[mm][2][hx * 2 + 0] = a1.x + c1.x;
            C[mm][2][hx * 2 + 1] = a1.y + c1.y;
            C[mm][3][hx * 2 + 0] = a1.z + c1.z;
            C[mm][3][hx * 2 + 1] = a1.w + c1.w;
        }

    gemm_T4s(smf, sb, wE0, C, tid, wm, wn, lane, pl4);   // += e @ We0
    gelu_ln_ep(C, smf, wm, wn, lane, F_PAR, F_PAR + 128, F_PAR + 256);
    write_T(C, smf, F_T, wm, wn, lane, 1);               // X over e tile
    __syncthreads();
    ZERO_C(C);
    gemm_T4s(smf, sb, wM1, C, tid, wm, wn, lane, pl4);   // MLP layer 1
    gelu_ln_ep(C, smf, wm, wn, lane, F_PAR + 384, F_PAR + 512, F_PAR + 640);

    // epilogue: residual (recomputed for layer0, re-read for layer1), scatter
    const float* w0 = smf + F_PAR + 768;
    const float* w1 = smf + F_PAR + 896;
    const float* bb = smf + F_PAR + 1024;
#pragma unroll
    for (int mm = 0; mm < 2; mm++)
#pragma unroll
        for (int hx = 0; hx < 2; hx++) {
            int row = wm * 32 + mm * 16 + hx * 8 + g;
            float ex0 = 0.f, ex1 = 0.f;
            if (layer0) {
                float2 xy = *(const float2*)(edges + 2 * (size_t)(base + row));
                ex0 = xy.x; ex1 = xy.y;
            }
            float* eo = e + (size_t)(base + row) * DM;
            float* ag = agg + (size_t)sI[64 + row] * DM;
#pragma unroll
            for (int nt = 0; nt < 4; nt++) {
                int col = wn * 32 + nt * 8 + q * 2;
                float r0v, r1v;
                if (layer0) {
                    r0v = fmaf(ex0, w0[col], fmaf(ex1, w1[col], bb[col]));
                    r1v = fmaf(ex0, w0[col + 1], fmaf(ex1, w1[col + 1], bb[col + 1]));
                } else {
                    float2 er = *(const float2*)(eo + col);
                    r0v = er.x; r1v = er.y;
                }
                float v0 = C[mm][nt][hx * 2 + 0] + r0v;
                float v1 = C[mm][nt][hx * 2 + 1] + r1v;
                if (layer0) *(float2*)(eo + col) = make_float2(v0, v1);
                RED2(ag + col, v0, v1);
            }
        }
}

// ---------------- node kernel (64 nodes per CTA) --------------------------------
__global__ __launch_bounds__(256, 3) void node_k(
    float* __restrict__ h, float* __restrict__ agg,
    const float* __restrict__ cnt,
    const float* __restrict__ wN0, const float* __restrict__ bn0c,
    const float* __restrict__ g0, const float* __restrict__ be0,
    const float* __restrict__ wM1, const float* __restrict__ b1,
    const float* __restrict__ g1, const float* __restrict__ be1,
    float* __restrict__ hs0, float* __restrict__ hr0,
    const float* __restrict__ wS0, const float* __restrict__ wR0, int tail,
    const float* __restrict__ wO, const float* __restrict__ ob,
    const float* __restrict__ og, const float* __restrict__ obb,
    const float* __restrict__ pw, const float* __restrict__ pb,
    float* __restrict__ outp, int do_out)
{
    extern __shared__ float smf[];
    uint32_t sb = smem_u32(smf);
    int tid = threadIdx.x, lane = tid & 31, wid = tid >> 5;
    int wm = wid >> 2, wn = wid & 3;
    int g = lane >> 2, q = lane & 3;
    int pl4 = (g * 4 + (q ^ fAg(g))) << 2;
    int base = blockIdx.x * 64;
    int r = tid >> 2, q4 = tid & 3;
    if (tid < 64) {
        int n = min(base + tid, NNODES - 1);
        smf[tid] = 1.0f / fmaxf(cnt[n], 1.0f);
    }
    if (tid < 128) {
        float* p = smf + F_PAR;
        p[tid] = bn0c[tid];      p[128 + tid] = g0[tid];
        p[256 + tid] = be0[tid]; p[384 + tid] = b1[tid];
        p[512 + tid] = g1[tid];  p[640 + tid] = be1[tid];
        if (do_out) {
            p[768 + tid]  = ob[tid];
            p[896 + tid]  = og[tid];
            p[1024 + tid] = obb[tid];
        }
    }
    int nr = min(base + r, NNODES - 1);
    stage_E32(smf + F_T + q4 * 2048, h + (size_t)nr * DM + q4 * 32, r);

    // GEMM1: K=256, agg chunks staged in-place into consumed T slots
    float C[2][4][4];
    ZERO_C(C);
    copy_w_async(sb + F_W * 4, wN0, tid); CP_COMMIT();
    CP_WAIT0(); __syncthreads();
#pragma unroll 1
    for (int c = 0; c < 8; c++) {
        if (c < 7) {
            int cn = c + 1;
            copy_w_async(sb + F_W * 4 + (cn & 1) * 16384, wN0 + cn * 4096, tid);
            CP_COMMIT();
            if (cn >= 4)
                stage_Af8s(smf + F_T + (cn & 3) * 2048,
                           agg + (size_t)nr * DM + ((cn & 3) << 5) + q4 * 8,
                           r, q4, smf[r]);
        }
        chunk_mma(smf + F_T + (c & 3) * 2048, smf + F_W + (c & 1) * 4096,
                  C, wm, wn, lane, pl4);
        CP_WAIT0();
        __syncthreads();
    }
    // re-zero this CTA's agg rows for the next layer (replaces init_k relaunch)
    if (tail) {
        float4 z = make_float4(0.f, 0.f, 0.f, 0.f);
        float4* az = (float4*)(agg + (size_t)nr * DM + q4 * 32);
#pragma unroll
        for (int i = 0; i < 8; i++) az[i] = z;
    }
    gelu_ln_ep(C, smf, wm, wn, lane, F_PAR, F_PAR + 128, F_PAR + 256);
    write_T(C, smf, F_T, wm, wn, lane, 1);
    __syncthreads();
    ZERO_C(C);
    gemm_T4s(smf, sb, wM1, C, tid, wm, wn, lane, pl4);   // MLP layer 1
    gelu_ln_ep(C, smf, wm, wn, lane, F_PAR + 384, F_PAR + 512, F_PAR + 640);

    // epilogue: h_new = C + h; store h unless final layer; keep h_new in C
#pragma unroll
    for (int mm = 0; mm < 2; mm++)
#pragma unroll
        for (int hx = 0; hx < 2; hx++) {
            int row = wm * 32 + mm * 16 + hx * 8 + g;
            if (base + row >= NNODES) continue;
            float* ho = h + (size_t)(base + row) * DM;
#pragma unroll
            for (int nt = 0; nt < 4; nt++) {
                int col = wn * 32 + nt * 8 + q * 2;
                float2 hv = *(const float2*)(ho + col);
                float v0 = C[mm][nt][hx * 2 + 0] + hv.x;
                float v1 = C[mm][nt][hx * 2 + 1] + hv.y;
                if (!do_out) *(float2*)(ho + col) = make_float2(v0, v1);
                C[mm][nt][hx * 2 + 0] = v0;
                C[mm][nt][hx * 2 + 1] = v1;
            }
        }

    if (tail) {
        __syncthreads();
        write_T(C, smf, F_T, wm, wn, lane, 1);     // X = tf32(h_new)
        __syncthreads();
        ZERO_C(C);
        gemm_T4s(smf, sb, wS0, C, tid, wm, wn, lane, pl4);
        store_perm(C, hs0, base, wm, wn, g, q);
        ZERO_C(C);
        gemm_T4s(smf, sb, wR0, C, tid, wm, wn, lane, pl4);
        store_perm(C, hr0, base, wm, wn, g, q);
    }
    if (do_out) {
        __syncthreads();
        write_T(C, smf, F_T, wm, wn, lane, 0);     // exact h_new
        __syncthreads();
        ZERO_C(C);
        gemm_T4s(smf, sb, wO, C, tid, wm, wn, lane, pl4);
        gelu_ln_ep(C, smf, wm, wn, lane, F_PAR + 768, F_PAR + 896, F_PAR + 1024);
        write_T(C, smf, F_T, wm, wn, lane, 0);
        float* sPw = smf + F_W;
        for (int i = tid; i < 128 * PREDL; i += 256) sPw[i] = pw[i];
        if (tid < PREDL) smf[F_W + 128 * PREDL + tid] = pb[tid];
        __syncthreads();
        if (base + r < NNODES) {
            ROWBASE(r, rb, fg);
            float acc[6];
#pragma unroll
            for (int j = 0; j < 6; j++)
                acc[j] = smf[F_W + 128 * PREDL + q4 * 6 + j];
#pragma unroll 1
            for (int ch = 0; ch < 4; ch++) {
                const float* X = smf + F_T + ch * 2048;
#pragma unroll
                for (int j = 0; j < 32; j++) {
                    float xv = X[AFIDX(rb, fg, j)];
                    const float* pr = sPw + (ch * 32 + j) * PREDL + q4 * 6;
#pragma unroll
                    for (int o = 0; o < 6; o++) acc[o] = fmaf(xv, pr[o], acc[o]);
                }
            }
            float* op = outp + (size_t)(base + r) * PREDL + q4 * 6;
#pragma unroll
            for (int j = 0; j < 6; j++) op[j] = acc[j];
        }
    }
}

// ---------------- node embedding (+ permuted hs0/hr0 for layer 0) ---------------
__global__ __launch_bounds__(256, 3) void emb_k(
    const float* __restrict__ nodes, const float* __restrict__ wE,
    const float* __restrict__ bias, float* __restrict__ h,
    float* __restrict__ hs0, float* __restrict__ hr0,
    const float* __restrict__ wS0, const float* __restrict__ wR0)
{
    extern __shared__ float smf[];
    uint32_t sb = smem_u32(smf);
    int tid = threadIdx.x, lane = tid & 31, wid = tid >> 5;
    int wm = wid >> 2, wn = wid & 3;
    int g = lane >> 2, q = lane & 3;
    int pl4 = (g * 4 + (q ^ fAg(g))) << 2;
    int base = blockIdx.x * 64;
    int r = tid >> 2, q4 = tid & 3;
    if (tid < 128) smf[F_PAR + tid] = bias[tid];
    int nr = min(base + r, NNODES - 1);
    const float* src = nodes + (size_t)nr * 288;

    // streamed GEMM over K=288: A streams through T[0]/T[1]
    float C[2][4][4];
    ZERO_C(C);
    copy_w_async(sb + F_W * 4, wE, tid); CP_COMMIT();
    stage_Af8(smf + F_T, src + q4 * 8, r, q4);
    CP_WAIT0(); __syncthreads();
#pragma unroll 1
    for (int c = 0; c < 9; c++) {
        if (c < 8) {
            int cn = c + 1;
            copy_w_async(sb + F_W * 4 + (cn & 1) * 16384, wE + cn * 4096, tid);
            CP_COMMIT();
            stage_Af8(smf + F_T + (cn & 1) * 2048, src + cn * 32 + q4 * 8, r, q4);
        }
        chunk_mma(smf + F_T + (c & 1) * 2048, smf + F_W + (c & 1) * 4096,
                  C, wm, wn, lane, pl4);
        CP_WAIT0();
        __syncthreads();
    }
    // h = C + bias (direct store), keep h in C for tails
#pragma unroll
    for (int mm = 0; mm < 2; mm++)
#pragma unroll
        for (int hx = 0; hx < 2; hx++) {
            int row = wm * 32 + mm * 16 + hx * 8 + g;
            float* ho = h + (size_t)(base + row) * DM;
#pragma unroll
            for (int nt = 0; nt < 4; nt++) {
                int col = wn * 32 + nt * 8 + q * 2;
                float v0 = C[mm][nt][hx * 2 + 0] + smf[F_PAR + col];
                float v1 = C[mm][nt][hx * 2 + 1] + smf[F_PAR + col + 1];
                if (base + row < NNODES)
                    *(float2*)(ho + col) = make_float2(v0, v1);
                C[mm][nt][hx * 2 + 0] = v0;
                C[mm][nt][hx * 2 + 1] = v1;
            }
        }
    write_T(C, smf, F_T, wm, wn, lane, 1);    // X = tf32(h)
    __syncthreads();
    ZERO_C(C);
    gemm_T4s(smf, sb, wS0, C, tid, wm, wn, lane, pl4);
    store_perm(C, hs0, base, wm, wn, g, q);
    ZERO_C(C);
    gemm_T4s(smf, sb, wR0, C, tid, wm, wn, lane, pl4);
    store_perm(C, hr0, base, wm, wn, g, q);
}

// ---------------- launch ------------------------------------------------------
extern "C" void kernel_launch(void* const* d_in, const int* in_sizes, int n_in,
                              void* d_out, int out_size)
{
    const float* nodes        = (const float*)d_in[0];
    const float* edges        = (const float*)d_in[1];
    const int*   senders      = (const int*)d_in[2];
    const int*   receivers    = (const int*)d_in[3];
    const float* w_node_emb   = (const float*)d_in[4];
    const float* b_node_emb   = (const float*)d_in[5];
    const float* w_edge_emb   = (const float*)d_in[6];
    const float* b_edge_emb   = (const float*)d_in[7];
    const float* edge_proj_w  = (const float*)d_in[8];
    const float* edge_proj_b  = (const float*)d_in[9];
    const float* node_proj_w  = (const float*)d_in[10];
    const float* node_proj_b  = (const float*)d_in[11];
    const float* edge_mlp_w   = (const float*)d_in[12];
    const float* edge_mlp_b   = (const float*)d_in[13];
    const float* edge_ln_g    = (const float*)d_in[14];
    const float* edge_ln_b    = (const float*)d_in[15];
    const float* node_mlp_w   = (const float*)d_in[16];
    const float* node_mlp_b   = (const float*)d_in[17];
    const float* node_ln_g    = (const float*)d_in[18];
    const float* node_ln_b    = (const float*)d_in[19];
    const float* mlp_out_w    = (const float*)d_in[20];
    const float* mlp_out_b    = (const float*)d_in[21];
    const float* mlp_out_g    = (const float*)d_in[22];
    const float* mlp_out_beta = (const float*)d_in[23];
    const float* proj_w       = (const float*)d_in[24];
    const float* proj_b       = (const float*)d_in[25];
    float* out = (float*)d_out;

    float *h, *e, *agg, *cnt, *wt, *hs, *hr, *cw;
    cudaGetSymbolAddress((void**)&h,   g_h);
    cudaGetSymbolAddress((void**)&e,   g_e);
    cudaGetSymbolAddress((void**)&agg, g_agg);
    cudaGetSymbolAddress((void**)&cnt, g_cnt);
    cudaGetSymbolAddress((void**)&wt,  g_wt);
    cudaGetSymbolAddress((void**)&hs,  g_hs);
    cudaGetSymbolAddress((void**)&hr,  g_hr);
    cudaGetSymbolAddress((void**)&cw,  g_cw);

    cudaFuncSetAttribute(edge_k, cudaFuncAttributeMaxDynamicSharedMemorySize, SMEMB);
    cudaFuncSetAttribute(node_k, cudaFuncAttributeMaxDynamicSharedMemorySize, SMEMB);
    cudaFuncSetAttribute(emb_k,  cudaFuncAttributeMaxDynamicSharedMemorySize, SMEMB);

    int nblk = (NNODES + 63) / 64;  // 313

    compose_k<<<1284, 128>>>(edge_proj_w, edge_proj_b, edge_mlp_w, edge_mlp_b,
                             node_proj_w, node_proj_b, node_mlp_w, node_mlp_b, cw);
    prep_frag<<<148, 256>>>(cw, edge_mlp_w, node_mlp_w, mlp_out_w, w_node_emb,
                            wt, cnt);
    init_k<<<2500 + (NEDGES + 255) / 256, 256>>>((float4*)agg, receivers, cnt);
    emb_k<<<nblk, 256, SMEMB>>>(nodes, wt + W_EMB * 4096, b_node_emb, h,
                                hs, hr, wt + W_S0(0) * 4096, wt + W_R0(0) * 4096);
    for (int l = 0; l < 2; l++) {
        edge_k<<<NEDGES / 64, 256, SMEMB>>>(
            e, edges, senders, receivers, hs, hr,
            w_edge_emb, b_edge_emb,
            wt + W_E0(l) * 4096, cw + l * CWL + 81920,
            edge_ln_g + (l * 2 + 0) * 128, edge_ln_b + (l * 2 + 0) * 128,
            wt + W_M1E(l) * 4096, edge_mlp_b + (l * 2 + 1) * 128,
            edge_ln_g + (l * 2 + 1) * 128, edge_ln_b + (l * 2 + 1) * 128,
            agg, l == 0);
        node_k<<<nblk, 256, SMEMB>>>(
            h, agg, cnt,
            wt + W_N0(l) * 4096, cw + l * CWL + 82048,
            node_ln_g + (l * 2 + 0) * 128, node_ln_b + (l * 2 + 0) * 128,
            wt + W_M1N(l) * 4096, node_mlp_b + (l * 2 + 1) * 128,
            node_ln_g + (l * 2 + 1) * 128, node_ln_b + (l * 2 + 1) * 128,
            hs, hr, wt + W_S0(1) * 4096, wt + W_R0(1) * 4096, l == 0,
            wt + W_OUT * 4096, mlp_out_b, mlp_out_g, mlp_out_beta,
            proj_w, proj_b, out, l == 1);
    }
}

// round 16
// speedup vs baseline: 1.5445x; 1.0277x over previous
#include <cuda_runtime.h>
#include <cstdint>

#define NNODES 20000
#define NEDGES 320000
#define DM 128
#define PREDL 24

// ---------------- device scratch ----------------------------------------------
__device__ float g_h[NNODES * DM];
__device__ float g_e[(size_t)NEDGES * DM];
__device__ float g_agg[NNODES * DM];
__device__ float g_cnt[NNODES];
__device__ float g_hs[NNODES * DM];     // (h @ Ws0) permuted
__device__ float g_hr[NNODES * DM];     // (h @ Wr0) permuted
#define CWL 82176
__device__ float g_cw[2 * CWL];         // composed weights (fp32)
__device__ float g_wt[69 * 4096];       // fragment-layout weights (tf32)

// g_wt chunk offsets
#define W_E0(l)  ((l) * 4)
#define W_M1E(l) (8 + (l) * 4)
#define W_N0(l)  (16 + (l) * 8)
#define W_M1N(l) (32 + (l) * 4)
#define W_S0(l)  (40 + (l) * 8)
#define W_R0(l)  (44 + (l) * 8)
#define W_OUT    56
#define W_EMB    60

// ---------------- smem float offsets (M=64 tile) --------------------------------
#define F_SUM 128               // 256
#define F_SQ  384               // 256
#define F_PAR 640               // 1152 params
#define F_W   1792              // 2 x 4096 W double buffer
#define F_T   (F_W + 8192)      // 4 x 2048 activation tile
#define SMEMB ((F_T + 8192) * 4)   // 72704 B -> 3 CTAs/SM

// ---------------- helpers ------------------------------------------------------
__device__ __forceinline__ uint32_t tfr(float x) {
    uint32_t r;
    asm("cvt.rna.tf32.f32 %0, %1;" : "=r"(r) : "f"(x));
    return r;
}
__device__ __forceinline__ float tff(float x) { return __uint_as_float(tfr(x)); }

__device__ __forceinline__ uint32_t smem_u32(const void* p) {
    uint32_t a;
    asm("{ .reg .u64 t; cvta.to.shared.u64 t, %1; cvt.u32.u64 %0, t; }"
        : "=r"(a) : "l"(p));
    return a;
}

__device__ __forceinline__ void mma8(float c[4], uint32_t a0, uint32_t a1,
                                     uint32_t a2, uint32_t a3,
                                     uint32_t b0, uint32_t b1) {
    asm volatile(
        "mma.sync.aligned.m16n8k8.row.col.f32.tf32.tf32.f32 "
        "{%0,%1,%2,%3}, {%4,%5,%6,%7}, {%8,%9}, {%0,%1,%2,%3};"
        : "+f"(c[0]), "+f"(c[1]), "+f"(c[2]), "+f"(c[3])
        : "r"(a0), "r"(a1), "r"(a2), "r"(a3), "r"(b0), "r"(b1));
}

// HW tanh (MUFU, sm_75+)
__device__ __forceinline__ float tanh_hw(float x) {
    float r;
    asm("tanh.approx.f32 %0, %1;" : "=f"(r) : "f"(x));
    return r;
}
__device__ __forceinline__ float geluf(float x) {
    float x3 = x * x * x;
    return 0.5f * x * (1.0f + tanh_hw(fmaf(0.044715f * 0.7978845608028654f, x3,
                                           0.7978845608028654f * x)));
}

__device__ __forceinline__ int fAg(int g) { return (g ^ (g >> 2)) & 3; }

// A-fragment index in a 2048-float chunk (64 rows x 32 k)
__device__ __forceinline__ int aidx(int row, int kl) {
    int wm = row >> 5, mm = (row >> 4) & 1, r8 = (row >> 3) & 1, g = row & 7;
    int kk = kl >> 3, k4 = (kl >> 2) & 1, tig = kl & 3;
    return (((kk * 2 + wm) * 2 + mm) << 7) + ((g * 4 + (tig ^ fAg(g))) << 2)
           + r8 + (k4 << 1);
}
// B-fragment index in a 4096-float chunk
__device__ __forceinline__ int bidx(int kl, int n) {
    int kk = kl >> 3, k4 = (kl >> 2) & 1, tig = kl & 3;
    int wn = n >> 5, ntp = (n >> 4) & 1, ntb = (n >> 3) & 1, gq = n & 7;
    return (((kk * 4 + wn) * 2 + ntp) << 7) + ((gq * 4 + tig) << 2)
           + ntb * 2 + k4;
}

#define CP16(daddr, src) asm volatile( \
    "cp.async.cg.shared.global [%0], [%1], 16;" :: "r"(daddr), "l"(src))
#define CP_COMMIT() asm volatile("cp.async.commit_group;" ::: "memory")
#define CP_WAIT0()  asm volatile("cp.async.wait_group 0;" ::: "memory")

// one 4096-float W chunk via cp.async (256 threads x 4 x 16B)
__device__ __forceinline__ void copy_w_async(uint32_t dsts,
                                             const float* __restrict__ src,
                                             int tid) {
    CP16(dsts + tid * 16, src + tid * 4);
    CP16(dsts + (tid + 256) * 16, src + (tid + 256) * 4);
    CP16(dsts + (tid + 512) * 16, src + (tid + 512) * 4);
    CP16(dsts + (tid + 768) * 16, src + (tid + 768) * 4);
}

// one 32-wide K chunk; warp covers 32 rows x 32 cols (A chunk = 2048 floats)
__device__ __forceinline__ void chunk_mma(const float* __restrict__ sA,
                                          const float* __restrict__ sW,
                                          float C[2][4][4], int wm, int wn,
                                          int lane, int pl4) {
#pragma unroll
    for (int kk = 0; kk < 4; kk++) {
        float4 b0 = *(const float4*)(sW + (((kk * 4 + wn) * 2 + 0) << 7)
                                     + (lane << 2));
        float4 b1 = *(const float4*)(sW + (((kk * 4 + wn) * 2 + 1) << 7)
                                     + (lane << 2));
#pragma unroll
        for (int mm = 0; mm < 2; mm++) {
            float4 av = *(const float4*)(sA + (((kk * 2 + wm) * 2 + mm) << 7) + pl4);
            uint32_t a0 = __float_as_uint(av.x), a1 = __float_as_uint(av.y);
            uint32_t a2 = __float_as_uint(av.z), a3 = __float_as_uint(av.w);
            mma8(C[mm][0], a0, a1, a2, a3,
                 __float_as_uint(b0.x), __float_as_uint(b0.y));
            mma8(C[mm][1], a0, a1, a2, a3,
                 __float_as_uint(b0.z), __float_as_uint(b0.w));
            mma8(C[mm][2], a0, a1, a2, a3,
                 __float_as_uint(b1.x), __float_as_uint(b1.y));
            mma8(C[mm][3], a0, a1, a2, a3,
                 __float_as_uint(b1.z), __float_as_uint(b1.w));
        }
    }
}

__device__ __forceinline__ void stage_Af8(float* chunk, const float* __restrict__ src,
                                          int r, int q4) {
    float4 v0 = *(const float4*)(src);
    float4 v1 = *(const float4*)(src + 4);
    chunk[aidx(r, q4 * 8 + 0)] = tff(v0.x);
    chunk[aidx(r, q4 * 8 + 1)] = tff(v0.y);
    chunk[aidx(r, q4 * 8 + 2)] = tff(v0.z);
    chunk[aidx(r, q4 * 8 + 3)] = tff(v0.w);
    chunk[aidx(r, q4 * 8 + 4)] = tff(v1.x);
    chunk[aidx(r, q4 * 8 + 5)] = tff(v1.y);
    chunk[aidx(r, q4 * 8 + 6)] = tff(v1.z);
    chunk[aidx(r, q4 * 8 + 7)] = tff(v1.w);
}
__device__ __forceinline__ void stage_Af8s(float* chunk, const float* __restrict__ src,
                                           int r, int q4, float sc) {
    float4 v0 = *(const float4*)(src);
    float4 v1 = *(const float4*)(src + 4);
    chunk[aidx(r, q4 * 8 + 0)] = tff(v0.x * sc);
    chunk[aidx(r, q4 * 8 + 1)] = tff(v0.y * sc);
    chunk[aidx(r, q4 * 8 + 2)] = tff(v0.z * sc);
    chunk[aidx(r, q4 * 8 + 3)] = tff(v0.w * sc);
    chunk[aidx(r, q4 * 8 + 4)] = tff(v1.x * sc);
    chunk[aidx(r, q4 * 8 + 5)] = tff(v1.y * sc);
    chunk[aidx(r, q4 * 8 + 6)] = tff(v1.z * sc);
    chunk[aidx(r, q4 * 8 + 7)] = tff(v1.w * sc);
}

// stage 32 cols of a row EXACT into A-frag chunk
__device__ __forceinline__ void stage_E32(float* chunk, const float* __restrict__ src,
                                          int r) {
#pragma unroll
    for (int i = 0; i < 8; i++) {
        float4 v = *(const float4*)(src + i * 4);
        chunk[aidx(r, i * 4 + 0)] = v.x;
        chunk[aidx(r, i * 4 + 1)] = v.y;
        chunk[aidx(r, i * 4 + 2)] = v.z;
        chunk[aidx(r, i * 4 + 3)] = v.w;
    }
}

__device__ __forceinline__ void write_T(float C[2][4][4], float* smf, int fbase,
                                        int wm, int wn, int lane, int cvt) {
    int g = lane >> 2, q = lane & 3;
#pragma unroll
    for (int mm = 0; mm < 2; mm++)
#pragma unroll
        for (int hx = 0; hx < 2; hx++) {
            int row = wm * 32 + mm * 16 + hx * 8 + g;
#pragma unroll
            for (int nt = 0; nt < 4; nt++)
#pragma unroll
                for (int s = 0; s < 2; s++) {
                    int col = wn * 32 + nt * 8 + q * 2 + s;
                    float v = C[mm][nt][hx * 2 + s];
                    smf[fbase + (col >> 5) * 2048 + aidx(row, col & 31)] =
                        cvt ? tff(v) : v;
                }
        }
}

__device__ __forceinline__ void gelu_ln_ep(float C[2][4][4], float* smf,
                                           int wm, int wn, int lane,
                                           int pb, int pg, int pbe) {
    int g = lane >> 2, q = lane & 3;
    float* sSum = smf + F_SUM;
    float* sSq  = smf + F_SQ;
#pragma unroll
    for (int mm = 0; mm < 2; mm++)
#pragma unroll
        for (int hx = 0; hx < 2; hx++) {
            float ps = 0.f, pq = 0.f;
#pragma unroll
            for (int nt = 0; nt < 4; nt++)
#pragma unroll
                for (int s = 0; s < 2; s++) {
                    int col = wn * 32 + nt * 8 + q * 2 + s;
                    float v = geluf(C[mm][nt][hx * 2 + s] + smf[pb + col]);
                    C[mm][nt][hx * 2 + s] = v;
                    ps += v; pq += v * v;
                }
            ps += __shfl_xor_sync(0xffffffffu, ps, 1);
            ps += __shfl_xor_sync(0xffffffffu, ps, 2);
            pq += __shfl_xor_sync(0xffffffffu, pq, 1);
            pq += __shfl_xor_sync(0xffffffffu, pq, 2);
            if (q == 0) {
                int row = wm * 32 + mm * 16 + hx * 8 + g;
                sSum[row * 4 + wn] = ps;
                sSq[row * 4 + wn]  = pq;
            }
        }
    __syncthreads();
#pragma unroll
    for (int mm = 0; mm < 2; mm++)
#pragma unroll
        for (int hx = 0; hx < 2; hx++) {
            int row = wm * 32 + mm * 16 + hx * 8 + g;
            float m = (sSum[row * 4] + sSum[row * 4 + 1]
                       + sSum[row * 4 + 2] + sSum[row * 4 + 3]) * (1.0f / 128.0f);
            float qv = (sSq[row * 4] + sSq[row * 4 + 1]
                        + sSq[row * 4 + 2] + sSq[row * 4 + 3]) * (1.0f / 128.0f);
            float rs = rsqrtf(qv - m * m + 1e-5f);
#pragma unroll
            for (int nt = 0; nt < 4; nt++)
#pragma unroll
                for (int s = 0; s < 2; s++) {
                    int col = wn * 32 + nt * 8 + q * 2 + s;
                    C[mm][nt][hx * 2 + s] =
                        (C[mm][nt][hx * 2 + s] - m) * rs * smf[pg + col] + smf[pbe + col];
                }
        }
}

#define ZERO_C(C) do { \
    _Pragma("unroll") for (int _m = 0; _m < 2; _m++) \
    _Pragma("unroll") for (int _n = 0; _n < 4; _n++) \
    _Pragma("unroll") for (int _s = 0; _s < 4; _s++) (C)[_m][_n][_s] = 0.f; } while (0)

// K=128 GEMM with chained prefetch.
// first_ready: chunk 0 of W already committed into buffer 0 (entry wait drains it).
// Wnext: prefetch next GEMM's chunk 0 into buffer 0 at c==3 (reader is buffer 1);
//        trailing wait/sync elided — caller's next phase carries a __syncthreads.
__device__ __forceinline__ void gemm_T4x(float* smf, uint32_t sb,
                                         const float* __restrict__ W,
                                         const float* __restrict__ Wnext,
                                         float C[2][4][4], int tid,
                                         int wm, int wn, int lane, int pl4,
                                         int first_ready) {
    if (!first_ready) { copy_w_async(sb + F_W * 4, W, tid); CP_COMMIT(); }
    CP_WAIT0(); __syncthreads();
#pragma unroll 1
    for (int c = 0; c < 4; c++) {
        if (c < 3) {
            copy_w_async(sb + F_W * 4 + ((c + 1) & 1) * 16384, W + (c + 1) * 4096, tid);
            CP_COMMIT();
        } else if (Wnext) {
            copy_w_async(sb + F_W * 4, Wnext, tid);   // buffer 0, reader on buffer 1
            CP_COMMIT();
        }
        chunk_mma(smf + F_T + c * 2048, smf + F_W + (c & 1) * 4096,
                  C, wm, wn, lane, pl4);
        if (c < 3) { CP_WAIT0(); __syncthreads(); }
    }
}

#define ROWBASE(r, rb, fg) \
    int rb = (((r) >> 5) * 2 + (((r) >> 4) & 1)) * 128 + ((r) & 7) * 16 \
             + (((r) >> 3) & 1); \
    int fg = fAg((r) & 7)
#define AFIDX(rb, fg, j) \
    (((j) >> 3) * 512 + (rb) + ((((j) & 3) ^ (fg)) << 2) + ((((j) >> 2) & 1) << 1))

#define RED2(p, a, b) asm volatile( \
    "red.global.add.v2.f32 [%0], {%1,%2};" :: "l"(p), "f"(a), "f"(b) : "memory")

// direct permuted store of C fragments to gout (matches edge gather layout)
__device__ __forceinline__ void store_perm(const float C[2][4][4],
                                           float* __restrict__ gout, int base,
                                           int wm, int wn, int g, int q) {
#pragma unroll
    for (int mm = 0; mm < 2; mm++)
#pragma unroll
        for (int hx = 0; hx < 2; hx++) {
            int row = wm * 32 + mm * 16 + hx * 8 + g;
            if (base + row >= NNODES) continue;
            float* go = gout + (size_t)(base + row) * DM + wn * 32 + q * 8;
            float4 f0, f1;
            f0.x = C[mm][0][hx * 2 + 0]; f0.y = C[mm][0][hx * 2 + 1];
            f0.z = C[mm][1][hx * 2 + 0]; f0.w = C[mm][1][hx * 2 + 1];
            f1.x = C[mm][2][hx * 2 + 0]; f1.y = C[mm][2][hx * 2 + 1];
            f1.z = C[mm][3][hx * 2 + 0]; f1.w = C[mm][3][hx * 2 + 1];
            *(float4*)go = f0;
            *(float4*)(go + 4) = f1;
        }
}

// ---------------- compose: fp32 weight products --------------------------------
__global__ void compose_k(const float* __restrict__ epw, const float* __restrict__ epb,
                          const float* __restrict__ emw, const float* __restrict__ emb_b,
                          const float* __restrict__ npw, const float* __restrict__ npb,
                          const float* __restrict__ nmw, const float* __restrict__ nmb,
                          float* __restrict__ cw) {
    int bi = blockIdx.x, j = threadIdx.x;
    int l = bi / 642, rr = bi % 642;
    const float *A, *B;
    float* out;
    float extra = 0.f;
    if (rr < 384) {
        A = epw + (size_t)l * 384 * 128 + rr * 128;
        B = emw + (l * 2) * 16384;
        out = cw + l * CWL + rr * 128;
    } else if (rr < 640) {
        int r2 = rr - 384;
        A = npw + (size_t)l * 256 * 128 + r2 * 128;
        B = nmw + (l * 2) * 16384;
        out = cw + l * CWL + 49152 + r2 * 128;
    } else if (rr == 640) {
        A = epb + l * 128; B = emw + (l * 2) * 16384;
        out = cw + l * CWL + 81920;
        extra = emb_b[(l * 2) * 128 + j];
    } else {
        A = npb + l * 128; B = nmw + (l * 2) * 16384;
        out = cw + l * CWL + 82048;
        extra = nmb[(l * 2) * 128 + j];
    }
    float acc = extra;
    for (int k = 0; k < 128; k++) acc += A[k] * B[k * 128 + j];
    out[j] = acc;
}

// ---------------- prep: all weights -> B-frag chunks; zero cnt -----------------
__global__ void prep_frag(const float* __restrict__ cw,
                          const float* __restrict__ emw,
                          const float* __restrict__ nmw,
                          const float* __restrict__ mow,
                          const float* __restrict__ wemb,
                          float* __restrict__ wt, float* __restrict__ cnt) {
    int b = blockIdx.x, tid = threadIdx.x;
    if (b < 69) {
        const float* M; int c;
        if (b < 8)       { int l = b >> 2; c = b & 3; M = cw + l * CWL; }
        else if (b < 16) { int l = (b - 8) >> 2; c = (b - 8) & 3;
                           M = emw + (l * 2 + 1) * 16384; }
        else if (b < 32) { int l = (b - 16) >> 3; c = (b - 16) & 7;
                           M = cw + l * CWL + 49152; }
        else if (b < 40) { int l = (b - 32) >> 2; c = (b - 32) & 3;
                           M = nmw + (l * 2 + 1) * 16384; }
        else if (b < 56) { int l = (b - 40) >> 3; int s = (b - 40) & 7;
                           c = s & 3; M = cw + l * CWL + 16384 + (s >> 2) * 16384; }
        else if (b < 60) { c = b - 56; M = mow; }
        else             { c = b - 60; M = wemb; }
        int kl = tid >> 3, n0 = (tid & 7) * 16;
#pragma unroll
        for (int j = 0; j < 16; j++) {
            int n = n0 + j;
            wt[b * 4096 + bidx(kl, n)] = tff(M[(c * 32 + kl) * 128 + n]);
        }
    } else {
        int i = (b - 69) * 256 + tid;
        if (i < NNODES) cnt[i] = 0.f;
    }
}

// merged: zero agg (first 2500 blocks) + in-degree count (rest)
__global__ void init_k(float4* __restrict__ agg4, const int* __restrict__ rcv,
                       float* __restrict__ cnt) {
    int b = blockIdx.x;
    if (b < 2500) {
        int i = b * 256 + threadIdx.x;
        if (i < NNODES * 32) agg4[i] = make_float4(0.f, 0.f, 0.f, 0.f);
    } else {
        int i = (b - 2500) * 256 + threadIdx.x;
        if (i < NEDGES) atomicAdd(cnt + rcv[i], 1.0f);
    }
}

// ---------------- edge kernel (64 edges per CTA) --------------------------------
__global__ __launch_bounds__(256, 3) void edge_k(
    float* __restrict__ e, const float* __restrict__ edges,
    const int* __restrict__ snd, const int* __restrict__ rcv,
    const float* __restrict__ hs0, const float* __restrict__ hr0,
    const float* __restrict__ wem, const float* __restrict__ bem,
    const float* __restrict__ wE0, const float* __restrict__ b0c,
    const float* __restrict__ g0, const float* __restrict__ be0,
    const float* __restrict__ wM1, const float* __restrict__ b1,
    const float* __restrict__ g1, const float* __restrict__ be1,
    float* __restrict__ agg, int layer0)
{
    extern __shared__ float smf[];
    uint32_t sb = smem_u32(smf);
    int tid = threadIdx.x, lane = tid & 31, wid = tid >> 5;
    int wm = wid >> 2, wn = wid & 3;
    int g = lane >> 2, q = lane & 3;
    int pl4 = (g * 4 + (q ^ fAg(g))) << 2;
    int base = blockIdx.x * 64;
    int r = tid >> 2, q4 = tid & 3;

    // hoisted: first W chunk in flight while we stage everything else
    copy_w_async(sb + F_W * 4, wE0, tid); CP_COMMIT();

    int* sI = (int*)smf;
    if (tid < 64)        sI[tid] = snd[base + tid];
    else if (tid < 128)  sI[tid] = rcv[base + tid - 64];
    if (tid < 128) {
        float* p = smf + F_PAR;
        p[tid] = b0c[tid];       p[128 + tid] = g0[tid];
        p[256 + tid] = be0[tid]; p[384 + tid] = b1[tid];
        p[512 + tid] = g1[tid];  p[640 + tid] = be1[tid];
        if (layer0) {
            p[768 + tid]  = wem[tid];
            p[896 + tid]  = wem[128 + tid];
            p[1024 + tid] = bem[tid];
        }
    }
    if (layer0) {
        __syncthreads();   // wem/bem visible
        float2 xy = *(const float2*)(edges + 2 * (size_t)(base + r));
        const float* w0 = smf + F_PAR + 768;
        const float* w1 = smf + F_PAR + 896;
        const float* bb = smf + F_PAR + 1024;
        float* Tc = smf + F_T + q4 * 2048;
#pragma unroll
        for (int i = 0; i < 32; i++) {
            int col = q4 * 32 + i;
            Tc[aidx(r, i)] =
                tff(fmaf(xy.x, w0[col], fmaf(xy.y, w1[col], bb[col])));
        }
    } else {
        stage_E32(smf + F_T + q4 * 2048,
                  e + (size_t)(base + r) * DM + q4 * 32, r);
    }
    __syncthreads();

    // C init = gathered hs0p + hr0p (permuted layout, coalesced 32B)
    float C[2][4][4];
#pragma unroll
    for (int mm = 0; mm < 2; mm++)
#pragma unroll
        for (int hx = 0; hx < 2; hx++) {
            int row = wm * 32 + mm * 16 + hx * 8 + g;
            const float4* hp = (const float4*)(hs0 + (size_t)sI[row] * DM
                                               + wn * 32 + q * 8);
            const float4* rp = (const float4*)(hr0 + (size_t)sI[64 + row] * DM
                                               + wn * 32 + q * 8);
            float4 a0 = hp[0], a1 = hp[1], c0 = rp[0], c1 = rp[1];
            C[mm][0][hx * 2 + 0] = a0.x + c0.x;
            C[mm][0][hx * 2 + 1] = a0.y + c0.y;
            C[mm][1][hx * 2 + 0] = a0.z + c0.z;
            C[mm][1][hx * 2 + 1] = a0.w + c0.w;
            C[mm][2][hx * 2 + 0] = a1.x + c1.x;
            C[mm][2][hx * 2 + 1] = a1.y + c1.y;
            C[mm][3][hx * 2 + 0] = a1.z + c1.z;
            C[mm][3][hx * 2 + 1] = a1.w + c1.w;
        }

    gemm_T4x(smf, sb, wE0, wM1, C, tid, wm, wn, lane, pl4, 1);  // += e @ We0
    gelu_ln_ep(C, smf, wm, wn, lane, F_PAR, F_PAR + 128, F_PAR + 256);
    write_T(C, smf, F_T, wm, wn, lane, 1);               // X over e tile
    __syncthreads();
    ZERO_C(C);
    gemm_T4x(smf, sb, wM1, 0, C, tid, wm, wn, lane, pl4, 1);    // MLP layer 1
    gelu_ln_ep(C, smf, wm, wn, lane, F_PAR + 384, F_PAR + 512, F_PAR + 640);

    // epilogue: residual (recomputed for layer0, re-read for layer1), scatter
    const float* w0 = smf + F_PAR + 768;
    const float* w1 = smf + F_PAR + 896;
    const float* bb = smf + F_PAR + 1024;
#pragma unroll
    for (int mm = 0; mm < 2; mm++)
#pragma unroll
        for (int hx = 0; hx < 2; hx++) {
            int row = wm * 32 + mm * 16 + hx * 8 + g;
            float ex0 = 0.f, ex1 = 0.f;
            if (layer0) {
                float2 xy = *(const float2*)(edges + 2 * (size_t)(base + row));
                ex0 = xy.x; ex1 = xy.y;
            }
            float* eo = e + (size_t)(base + row) * DM;
            float* ag = agg + (size_t)sI[64 + row] * DM;
#pragma unroll
            for (int nt = 0; nt < 4; nt++) {
                int col = wn * 32 + nt * 8 + q * 2;
                float r0v, r1v;
                if (layer0) {
                    r0v = fmaf(ex0, w0[col], fmaf(ex1, w1[col], bb[col]));
                    r1v = fmaf(ex0, w0[col + 1], fmaf(ex1, w1[col + 1], bb[col + 1]));
                } else {
                    float2 er = *(const float2*)(eo + col);
                    r0v = er.x; r1v = er.y;
                }
                float v0 = C[mm][nt][hx * 2 + 0] + r0v;
                float v1 = C[mm][nt][hx * 2 + 1] + r1v;
                if (layer0) *(float2*)(eo + col) = make_float2(v0, v1);
                RED2(ag + col, v0, v1);
            }
        }
}

// ---------------- node kernel (64 nodes per CTA) --------------------------------
__global__ __launch_bounds__(256, 3) void node_k(
    float* __restrict__ h, float* __restrict__ agg,
    const float* __restrict__ cnt,
    const float* __restrict__ wN0, const float* __restrict__ bn0c,
    const float* __restrict__ g0, const float* __restrict__ be0,
    const float* __restrict__ wM1, const float* __restrict__ b1,
    const float* __restrict__ g1, const float* __restrict__ be1,
    float* __restrict__ hs0, float* __restrict__ hr0,
    const float* __restrict__ wS0, const float* __restrict__ wR0, int tail,
    const float* __restrict__ wO, const float* __restrict__ ob,
    const float* __restrict__ og, const float* __restrict__ obb,
    const float* __restrict__ pw, const float* __restrict__ pb,
    float* __restrict__ outp, int do_out)
{
    extern __shared__ float smf[];
    uint32_t sb = smem_u32(smf);
    int tid = threadIdx.x, lane = tid & 31, wid = tid >> 5;
    int wm = wid >> 2, wn = wid & 3;
    int g = lane >> 2, q = lane & 3;
    int pl4 = (g * 4 + (q ^ fAg(g))) << 2;
    int base = blockIdx.x * 64;
    int r = tid >> 2, q4 = tid & 3;

    // hoisted: first W chunk in flight while we stage everything else
    copy_w_async(sb + F_W * 4, wN0, tid); CP_COMMIT();

    if (tid < 64) {
        int n = min(base + tid, NNODES - 1);
        smf[tid] = 1.0f / fmaxf(cnt[n], 1.0f);
    }
    if (tid < 128) {
        float* p = smf + F_PAR;
        p[tid] = bn0c[tid];      p[128 + tid] = g0[tid];
        p[256 + tid] = be0[tid]; p[384 + tid] = b1[tid];
        p[512 + tid] = g1[tid];  p[640 + tid] = be1[tid];
        if (do_out) {
            p[768 + tid]  = ob[tid];
            p[896 + tid]  = og[tid];
            p[1024 + tid] = obb[tid];
        }
    }
    int nr = min(base + r, NNODES - 1);
    stage_E32(smf + F_T + q4 * 2048, h + (size_t)nr * DM + q4 * 32, r);

    // GEMM1: K=256, agg chunks staged in-place into consumed T slots.
    // At c==7: prefetch wM1 chunk0 into buffer 0 (reader on buffer 1); skip
    // the trailing wait/sync (LN below carries a __syncthreads).
    float C[2][4][4];
    ZERO_C(C);
    CP_WAIT0(); __syncthreads();
#pragma unroll 1
    for (int c = 0; c < 8; c++) {
        if (c < 7) {
            int cn = c + 1;
            copy_w_async(sb + F_W * 4 + (cn & 1) * 16384, wN0 + cn * 4096, tid);
            CP_COMMIT();
            if (cn >= 4)
                stage_Af8s(smf + F_T + (cn & 3) * 2048,
                           agg + (size_t)nr * DM + ((cn & 3) << 5) + q4 * 8,
                           r, q4, smf[r]);
        } else {
            copy_w_async(sb + F_W * 4, wM1, tid);
            CP_COMMIT();
        }
        chunk_mma(smf + F_T + (c & 3) * 2048, smf + F_W + (c & 1) * 4096,
                  C, wm, wn, lane, pl4);
        if (c < 7) { CP_WAIT0(); __syncthreads(); }
    }
    // re-zero this CTA's agg rows for the next layer (replaces init_k relaunch)
    if (tail) {
        float4 z = make_float4(0.f, 0.f, 0.f, 0.f);
        float4* az = (float4*)(agg + (size_t)nr * DM + q4 * 32);
#pragma unroll
        for (int i = 0; i < 8; i++) az[i] = z;
    }
    gelu_ln_ep(C, smf, wm, wn, lane, F_PAR, F_PAR + 128, F_PAR + 256);
    write_T(C, smf, F_T, wm, wn, lane, 1);
    __syncthreads();
    ZERO_C(C);
    gemm_T4x(smf, sb, wM1, tail ? wS0 : (do_out ? wO : 0),
             C, tid, wm, wn, lane, pl4, 1);               // MLP layer 1
    gelu_ln_ep(C, smf, wm, wn, lane, F_PAR + 384, F_PAR + 512, F_PAR + 640);

    // epilogue: h_new = C + h; store h unless final layer; keep h_new in C
#pragma unroll
    for (int mm = 0; mm < 2; mm++)
#pragma unroll
        for (int hx = 0; hx < 2; hx++) {
            int row = wm * 32 + mm * 16 + hx * 8 + g;
            if (base + row >= NNODES) continue;
            float* ho = h + (size_t)(base + row) * DM;
#pragma unroll
            for (int nt = 0; nt < 4; nt++) {
                int col = wn * 32 + nt * 8 + q * 2;
                float2 hv = *(const float2*)(ho + col);
                float v0 = C[mm][nt][hx * 2 + 0] + hv.x;
                float v1 = C[mm][nt][hx * 2 + 1] + hv.y;
                if (!do_out) *(float2*)(ho + col) = make_float2(v0, v1);
                C[mm][nt][hx * 2 + 0] = v0;
                C[mm][nt][hx * 2 + 1] = v1;
            }
        }

    if (tail) {
        __syncthreads();
        write_T(C, smf, F_T, wm, wn, lane, 1);     // X = tf32(h_new)
        __syncthreads();
        ZERO_C(C);
        gemm_T4x(smf, sb, wS0, wR0, C, tid, wm, wn, lane, pl4, 1);
        store_perm(C, hs0, base, wm, wn, g, q);
        ZERO_C(C);
        gemm_T4x(smf, sb, wR0, 0, C, tid, wm, wn, lane, pl4, 1);
        store_perm(C, hr0, base, wm, wn, g, q);
    }
    if (do_out) {
        __syncthreads();
        write_T(C, smf, F_T, wm, wn, lane, 0);     // exact h_new
        __syncthreads();
        ZERO_C(C);
        gemm_T4x(smf, sb, wO, 0, C, tid, wm, wn, lane, pl4, 1);
        gelu_ln_ep(C, smf, wm, wn, lane, F_PAR + 768, F_PAR + 896, F_PAR + 1024);
        write_T(C, smf, F_T, wm, wn, lane, 0);
        float* sPw = smf + F_W;
        for (int i = tid; i < 128 * PREDL; i += 256) sPw[i] = pw[i];
        if (tid < PREDL) smf[F_W + 128 * PREDL + tid] = pb[tid];
        __syncthreads();
        if (base + r < NNODES) {
            ROWBASE(r, rb, fg);
            float acc[6];
#pragma unroll
            for (int j = 0; j < 6; j++)
                acc[j] = smf[F_W + 128 * PREDL + q4 * 6 + j];
#pragma unroll 1
            for (int ch = 0; ch < 4; ch++) {
                const float* X = smf + F_T + ch * 2048;
#pragma unroll
                for (int j = 0; j < 32; j++) {
                    float xv = X[AFIDX(rb, fg, j)];
                    const float* pr = sPw + (ch * 32 + j) * PREDL + q4 * 6;
#pragma unroll
                    for (int o = 0; o < 6; o++) acc[o] = fmaf(xv, pr[o], acc[o]);
                }
            }
            float* op = outp + (size_t)(base + r) * PREDL + q4 * 6;
#pragma unroll
            for (int j = 0; j < 6; j++) op[j] = acc[j];
        }
    }
}

// ---------------- node embedding (+ permuted hs0/hr0 for layer 0) ---------------
__global__ __launch_bounds__(256, 3) void emb_k(
    const float* __restrict__ nodes, const float* __restrict__ wE,
    const float* __restrict__ bias, float* __restrict__ h,
    float* __restrict__ hs0, float* __restrict__ hr0,
    const float* __restrict__ wS0, const float* __restrict__ wR0)
{
    extern __shared__ float smf[];
    uint32_t sb = smem_u32(smf);
    int tid = threadIdx.x, lane = tid & 31, wid = tid >> 5;
    int wm = wid >> 2, wn = wid & 3;
    int g = lane >> 2, q = lane & 3;
    int pl4 = (g * 4 + (q ^ fAg(g))) << 2;
    int base = blockIdx.x * 64;
    int r = tid >> 2, q4 = tid & 3;
    if (tid < 128) smf[F_PAR + tid] = bias[tid];
    int nr = min(base + r, NNODES - 1);
    const float* src = nodes + (size_t)nr * 288;

    // streamed GEMM over K=288: A streams through T[0]/T[1]
    float C[2][4][4];
    ZERO_C(C);
    copy_w_async(sb + F_W * 4, wE, tid); CP_COMMIT();
    stage_Af8(smf + F_T, src + q4 * 8, r, q4);
    CP_WAIT0(); __syncthreads();
#pragma unroll 1
    for (int c = 0; c < 9; c++) {
        if (c < 8) {
            int cn = c + 1;
            copy_w_async(sb + F_W * 4 + (cn & 1) * 16384, wE + cn * 4096, tid);
            CP_COMMIT();
            stage_Af8(smf + F_T + (cn & 1) * 2048, src + cn * 32 + q4 * 8, r, q4);
        }
        chunk_mma(smf + F_T + (c & 1) * 2048, smf + F_W + (c & 1) * 4096,
                  C, wm, wn, lane, pl4);
        CP_WAIT0();
        __syncthreads();
    }
    // h = C + bias (direct store), keep h in C for tails
#pragma unroll
    for (int mm = 0; mm < 2; mm++)
#pragma unroll
        for (int hx = 0; hx < 2; hx++) {
            int row = wm * 32 + mm * 16 + hx * 8 + g;
            float* ho = h + (size_t)(base + row) * DM;
#pragma unroll
            for (int nt = 0; nt < 4; nt++) {
                int col = wn * 32 + nt * 8 + q * 2;
                float v0 = C[mm][nt][hx * 2 + 0] + smf[F_PAR + col];
                float v1 = C[mm][nt][hx * 2 + 1] + smf[F_PAR + col + 1];
                if (base + row < NNODES)
                    *(float2*)(ho + col) = make_float2(v0, v1);
                C[mm][nt][hx * 2 + 0] = v0;
                C[mm][nt][hx * 2 + 1] = v1;
            }
        }
    write_T(C, smf, F_T, wm, wn, lane, 1);    // X = tf32(h)
    __syncthreads();
    ZERO_C(C);
    gemm_T4x(smf, sb, wS0, wR0, C, tid, wm, wn, lane, pl4, 0);
    store_perm(C, hs0, base, wm, wn, g, q);
    ZERO_C(C);
    gemm_T4x(smf, sb, wR0, 0, C, tid, wm, wn, lane, pl4, 1);
    store_perm(C, hr0, base, wm, wn, g, q);
}

// ---------------- launch ------------------------------------------------------
extern "C" void kernel_launch(void* const* d_in, const int* in_sizes, int n_in,
                              void* d_out, int out_size)
{
    const float* nodes        = (const float*)d_in[0];
    const float* edges        = (const float*)d_in[1];
    const int*   senders      = (const int*)d_in[2];
    const int*   receivers    = (const int*)d_in[3];
    const float* w_node_emb   = (const float*)d_in[4];
    const float* b_node_emb   = (const float*)d_in[5];
    const float* w_edge_emb   = (const float*)d_in[6];
    const float* b_edge_emb   = (const float*)d_in[7];
    const float* edge_proj_w  = (const float*)d_in[8];
    const float* edge_proj_b  = (const float*)d_in[9];
    const float* node_proj_w  = (const float*)d_in[10];
    const float* node_proj_b  = (const float*)d_in[11];
    const float* edge_mlp_w   = (const float*)d_in[12];
    const float* edge_mlp_b   = (const float*)d_in[13];
    const float* edge_ln_g    = (const float*)d_in[14];
    const float* edge_ln_b    = (const float*)d_in[15];
    const float* node_mlp_w   = (const float*)d_in[16];
    const float* node_mlp_b   = (const float*)d_in[17];
    const float* node_ln_g    = (const float*)d_in[18];
    const float* node_ln_b    = (const float*)d_in[19];
    const float* mlp_out_w    = (const float*)d_in[20];
    const float* mlp_out_b    = (const float*)d_in[21];
    const float* mlp_out_g    = (const float*)d_in[22];
    const float* mlp_out_beta = (const float*)d_in[23];
    const float* proj_w       = (const float*)d_in[24];
    const float* proj_b       = (const float*)d_in[25];
    float* out = (float*)d_out;

    float *h, *e, *agg, *cnt, *wt, *hs, *hr, *cw;
    cudaGetSymbolAddress((void**)&h,   g_h);
    cudaGetSymbolAddress((void**)&e,   g_e);
    cudaGetSymbolAddress((void**)&agg, g_agg);
    cudaGetSymbolAddress((void**)&cnt, g_cnt);
    cudaGetSymbolAddress((void**)&wt,  g_wt);
    cudaGetSymbolAddress((void**)&hs,  g_hs);
    cudaGetSymbolAddress((void**)&hr,  g_hr);
    cudaGetSymbolAddress((void**)&cw,  g_cw);

    cudaFuncSetAttribute(edge_k, cudaFuncAttributeMaxDynamicSharedMemorySize, SMEMB);
    cudaFuncSetAttribute(node_k, cudaFuncAttributeMaxDynamicSharedMemorySize, SMEMB);
    cudaFuncSetAttribute(emb_k,  cudaFuncAttributeMaxDynamicSharedMemorySize, SMEMB);

    int nblk = (NNODES + 63) / 64;  // 313

    compose_k<<<1284, 128>>>(edge_proj_w, edge_proj_b, edge_mlp_w, edge_mlp_b,
                             node_proj_w, node_proj_b, node_mlp_w, node_mlp_b, cw);
    prep_frag<<<148, 256>>>(cw, edge_mlp_w, node_mlp_w, mlp_out_w, w_node_emb,
                            wt, cnt);
    init_k<<<2500 + (NEDGES + 255) / 256, 256>>>((float4*)agg, receivers, cnt);
    emb_k<<<nblk, 256, SMEMB>>>(nodes, wt + W_EMB * 4096, b_node_emb, h,
                                hs, hr, wt + W_S0(0) * 4096, wt + W_R0(0) * 4096);
    for (int l = 0; l < 2; l++) {
        edge_k<<<NEDGES / 64, 256, SMEMB>>>(
            e, edges, senders, receivers, hs, hr,
            w_edge_emb, b_edge_emb,
            wt + W_E0(l) * 4096, cw + l * CWL + 81920,
            edge_ln_g + (l * 2 + 0) * 128, edge_ln_b + (l * 2 + 0) * 128,
            wt + W_M1E(l) * 4096, edge_mlp_b + (l * 2 + 1) * 128,
            edge_ln_g + (l * 2 + 1) * 128, edge_ln_b + (l * 2 + 1) * 128,
            agg, l == 0);
        node_k<<<nblk, 256, SMEMB>>>(
            h, agg, cnt,
            wt + W_N0(l) * 4096, cw + l * CWL + 82048,
            node_ln_g + (l * 2 + 0) * 128, node_ln_b + (l * 2 + 0) * 128,
            wt + W_M1N(l) * 4096, node_mlp_b + (l * 2 + 1) * 128,
            node_ln_g + (l * 2 + 1) * 128, node_ln_b + (l * 2 + 1) * 128,
            hs, hr, wt + W_S0(1) * 4096, wt + W_R0(1) * 4096, l == 0,
            wt + W_OUT * 4096, mlp_out_b, mlp_out_g, mlp_out_beta,
            proj_w, proj_b, out, l == 1);
    }
}